// round 9
// baseline (speedup 1.0000x reference)
#include <cuda_runtime.h>
#include <cuda_bf16.h>
#include <cstdint>
#include <cstring>

// ---------------------------------------------------------------------------
// GraphSAGE (2-layer, mean agg) + graph-mean readout + linear classifier.
// R9: R8 with the decoupled-lookback race fixed (flag+value packed in one
// 64-bit word so readers see a consistent (flag,value) pair).
// 7 launches. Zero-state invariants: g_count / g_gs1 / g_gs2 / g_gcnt / g_state
// are zero at module load and restored by every kernel_launch call.
// ---------------------------------------------------------------------------

#define K_NODES  100000
#define K_EDGES  1600000
#define K_GRAPHS 64
#define K_DIM    128
#define K_CLS    8
#define K_NB     98            // ceil(100000/1024)
#define K_QUADS  (K_NODES * K_DIM / 4)

// scratch (static device memory; no allocations)
__device__ int   g_count [K_NODES];            // zero-invariant
__device__ int   g_rowptr[K_NODES + 1];
__device__ int   g_cursor[K_NODES];
__device__ int   g_esrc  [K_EDGES];
__device__ unsigned long long g_state[K_NB];   // packed (flag<<32)|value, zeroed by k_prep
__device__ float g_gs1   [K_GRAPHS * K_DIM];   // zero-invariant
__device__ float g_gs2   [K_GRAPHS * K_DIM];   // zero-invariant
__device__ int   g_gcnt  [K_GRAPHS];           // zero-invariant
__device__ float g_mean  [(size_t)K_NODES * K_DIM];
__device__ float g_h1    [(size_t)K_NODES * K_DIM];
__device__ __nv_bfloat16 g_hb  [(size_t)K_NODES * K_DIM];
__device__ __nv_bfloat16 g_h1b [(size_t)K_NODES * K_DIM];

// ---------------------------------------------------------------------------
// 0) prep: bf16 shadow of h + dst histogram (counts start zero) + state reset
__global__ void k_prep(const float* __restrict__ X, __nv_bfloat16* __restrict__ Y,
                       const int* __restrict__ dst) {
    int i = blockIdx.x * blockDim.x + threadIdx.x;
    if (i < K_NB) g_state[i] = 0ull;
    if (i < K_QUADS) {
        float4 v = *((const float4*)X + i);
        __nv_bfloat162 a = __floats2bfloat162_rn(v.x, v.y);
        __nv_bfloat162 b = __floats2bfloat162_rn(v.z, v.w);
        uint2 u;
        memcpy(&u.x, &a, 4);
        memcpy(&u.y, &b, 4);
        *((uint2*)Y + i) = u;
    }
    if (i < K_EDGES) atomicAdd(&g_count[dst[i]], 1);
}

// 1) single-pass scan (decoupled lookback, packed flag|value) -> rowptr,cursor;
//    re-zeroes counts for the next call.
__global__ void k_scan() {
    __shared__ int sm[256];
    __shared__ int sExcl;
    int b = blockIdx.x, t = threadIdx.x;
    int base = b * 1024 + t * 4;
    int c[4];
    int s = 0;
#pragma unroll
    for (int j = 0; j < 4; ++j) {
        int i = base + j;
        c[j] = (i < K_NODES) ? g_count[i] : 0;
        if (i < K_NODES) g_count[i] = 0;       // maintain zero-invariant
        s += c[j];
    }
    sm[t] = s;
    __syncthreads();
    for (int o = 1; o < 256; o <<= 1) {
        int u = (t >= o) ? sm[t - o] : 0;
        __syncthreads();
        sm[t] += u;
        __syncthreads();
    }
    int S = sm[255];                            // block total
    if (t == 0) {
        if (b == 0) {
            atomicExch(&g_state[0], (2ull << 32) | (unsigned int)S);
            sExcl = 0;
        } else {
            atomicExch(&g_state[b], (1ull << 32) | (unsigned int)S);
            int excl = 0, p = b - 1;
            while (true) {
                unsigned long long v = atomicAdd(&g_state[p], 0ull);
                unsigned int f = (unsigned int)(v >> 32);
                if (f == 0) continue;           // not published yet
                excl += (int)(unsigned int)v;
                if (f == 2) break;              // inclusive prefix: done
                --p;                            // aggregate: keep looking back
            }
            atomicExch(&g_state[b], (2ull << 32) | (unsigned int)(excl + S));
            sExcl = excl;
        }
    }
    __syncthreads();
    int off = sExcl + sm[t] - s;                // exclusive prefix for this thread
#pragma unroll
    for (int j = 0; j < 4; ++j) {
        int i = base + j;
        if (i < K_NODES) {
            g_rowptr[i] = off;
            g_cursor[i] = off;
        }
        off += c[j];
    }
    if (b == K_NB - 1 && t == 255) g_rowptr[K_NODES] = sExcl + S;
}

// 2) bucket fill: sort edge srcs by dst
__global__ void k_fill(const int* __restrict__ src, const int* __restrict__ dst) {
    int i = blockIdx.x * blockDim.x + threadIdx.x;
    if (i < K_EDGES) {
        int p = atomicAdd(&g_cursor[dst[i]], 1);
        g_esrc[p] = src[i];
    }
}

// ---------------------------------------------------------------------------
// gather helpers
__device__ __forceinline__ void bf16acc(uint2 u, float& ax, float& ay,
                                        float& az, float& aw) {
    __nv_bfloat162 p0, p1;
    memcpy(&p0, &u.x, 4);
    memcpy(&p1, &u.y, 4);
    float2 f0 = __bfloat1622float2(p0);
    float2 f1 = __bfloat1622float2(p1);
    ax += f0.x; ay += f0.y; az += f1.x; aw += f1.y;
}

__device__ __forceinline__ void gather_row(const __nv_bfloat16* __restrict__ X,
                                           int e0, int e1, int lane,
                                           float& ax, float& ay, float& az, float& aw) {
    int e = e0;
    for (; e + 8 <= e1; e += 8) {
        int s[8];
#pragma unroll
        for (int q = 0; q < 8; ++q) s[q] = g_esrc[e + q];
        uint2 u[8];
#pragma unroll
        for (int q = 0; q < 8; ++q)
            u[q] = *((const uint2*)(X + (size_t)s[q] * K_DIM) + lane);
#pragma unroll
        for (int q = 0; q < 8; ++q) bf16acc(u[q], ax, ay, az, aw);
    }
    for (; e + 4 <= e1; e += 4) {
        int s[4];
#pragma unroll
        for (int q = 0; q < 4; ++q) s[q] = g_esrc[e + q];
        uint2 u[4];
#pragma unroll
        for (int q = 0; q < 4; ++q)
            u[q] = *((const uint2*)(X + (size_t)s[q] * K_DIM) + lane);
#pragma unroll
        for (int q = 0; q < 4; ++q) bf16acc(u[q], ax, ay, az, aw);
    }
    for (; e < e1; ++e) {
        int s = g_esrc[e];
        uint2 u = *((const uint2*)(X + (size_t)s * K_DIM) + lane);
        bf16acc(u, ax, ay, az, aw);
    }
}

// 3) SpMM mean (layer 1): one warp per dst row -> g_mean
__global__ void k_spmm_bf16(const __nv_bfloat16* __restrict__ X, float* __restrict__ Y) {
    int w = (blockIdx.x * blockDim.x + threadIdx.x) >> 5;
    int lane = threadIdx.x & 31;
    if (w >= K_NODES) return;
    int e0 = g_rowptr[w], e1 = g_rowptr[w + 1];
    float ax = 0.f, ay = 0.f, az = 0.f, aw = 0.f;
    gather_row(X, e0, e1, lane, ax, ay, az, aw);
    float inv = (e1 > e0) ? 1.0f / (float)(e1 - e0) : 0.0f;
    float4 r;
    r.x = ax * inv; r.y = ay * inv; r.z = az * inv; r.w = aw * inv;
    *((float4*)(Y + (size_t)w * K_DIM) + lane) = r;
}

// ---------------------------------------------------------------------------
// 4) mma.sync tf32 dual GEMM with register-prefetch double buffering.
__device__ __forceinline__ uint32_t f2tf32(float x) {
    uint32_t u;
    asm("cvt.rna.tf32.f32 %0, %1;" : "=r"(u) : "f"(x));
    return u;
}
__device__ __forceinline__ void mma_tf32(float* c, uint32_t a0, uint32_t a1,
                                         uint32_t a2, uint32_t a3,
                                         uint32_t b0, uint32_t b1) {
    asm volatile(
        "mma.sync.aligned.m16n8k8.row.col.f32.tf32.tf32.f32 "
        "{%0,%1,%2,%3}, {%4,%5,%6,%7}, {%8,%9}, {%0,%1,%2,%3};"
        : "+f"(c[0]), "+f"(c[1]), "+f"(c[2]), "+f"(c[3])
        : "r"(a0), "r"(a1), "r"(a2), "r"(a3), "r"(b0), "r"(b1));
}

__global__ __launch_bounds__(256, 2)
void k_gemm_mma(const float* __restrict__ A1, const float* __restrict__ A2,
                const float* __restrict__ W1, const float* __restrict__ W2,
                const float* __restrict__ bias, float* __restrict__ C,
                __nv_bfloat16* __restrict__ Cb, int M) {
    __shared__ __align__(16) uint32_t Xs[32 * 132];
    __shared__ __align__(16) uint32_t Ws[32 * 128];
    int tid = threadIdx.x, wid = tid >> 5, lane = tid & 31;
    int grp = lane >> 2, tig = lane & 3;
    int warpM = wid & 3, warpN = wid >> 2;
    int rowBase = blockIdx.x * 128;
    int wr = warpM * 32;
    int wn = warpN * 64;

    int rloc = tid >> 3;
    int kq   = (tid & 7) << 2;
    int wkk  = tid >> 5;
    int wnn  = (tid & 31) << 2;

    float acc[2][8][4];
#pragma unroll
    for (int mt = 0; mt < 2; ++mt)
#pragma unroll
        for (int nt = 0; nt < 8; ++nt)
#pragma unroll
            for (int q = 0; q < 4; ++q) acc[mt][nt][q] = 0.0f;

    float4 ra[4], rw[4];
    {
#pragma unroll
        for (int i = 0; i < 4; ++i) {
            int grow = rowBase + rloc + i * 32; if (grow >= M) grow = M - 1;
            ra[i] = *(const float4*)&A1[(size_t)grow * K_DIM + kq];
        }
#pragma unroll
        for (int i = 0; i < 4; ++i) {
            int kk = wkk + i * 8;
            rw[i] = *(const float4*)&W1[(size_t)kk * K_DIM + wnn];
        }
    }

#pragma unroll 1
    for (int cc = 0; cc < 8; ++cc) {
        __syncthreads();
#pragma unroll
        for (int i = 0; i < 4; ++i) {
            int rr = rloc + i * 32;
            Xs[(kq + 0) * 132 + rr] = f2tf32(ra[i].x);
            Xs[(kq + 1) * 132 + rr] = f2tf32(ra[i].y);
            Xs[(kq + 2) * 132 + rr] = f2tf32(ra[i].z);
            Xs[(kq + 3) * 132 + rr] = f2tf32(ra[i].w);
        }
#pragma unroll
        for (int i = 0; i < 4; ++i) {
            int kk = wkk + i * 8;
            Ws[kk * 128 + wnn + 0] = f2tf32(rw[i].x);
            Ws[kk * 128 + wnn + 1] = f2tf32(rw[i].y);
            Ws[kk * 128 + wnn + 2] = f2tf32(rw[i].z);
            Ws[kk * 128 + wnn + 3] = f2tf32(rw[i].w);
        }
        __syncthreads();
        if (cc < 7) {
            int nc = cc + 1;
            const float* A = (nc >= 4) ? A2 : A1;
            const float* W = (nc >= 4) ? W2 : W1;
            int k0 = (nc & 3) * 32;
#pragma unroll
            for (int i = 0; i < 4; ++i) {
                int grow = rowBase + rloc + i * 32; if (grow >= M) grow = M - 1;
                ra[i] = *(const float4*)&A[(size_t)grow * K_DIM + k0 + kq];
            }
#pragma unroll
            for (int i = 0; i < 4; ++i) {
                int kk = wkk + i * 8;
                rw[i] = *(const float4*)&W[(size_t)(k0 + kk) * K_DIM + wnn];
            }
        }
#pragma unroll
        for (int ks = 0; ks < 4; ++ks) {
            int kk = ks * 8;
            uint32_t af[2][4];
#pragma unroll
            for (int mt = 0; mt < 2; ++mt) {
                int r = wr + mt * 16 + grp;
                af[mt][0] = Xs[(kk + tig)     * 132 + r];
                af[mt][1] = Xs[(kk + tig)     * 132 + r + 8];
                af[mt][2] = Xs[(kk + tig + 4) * 132 + r];
                af[mt][3] = Xs[(kk + tig + 4) * 132 + r + 8];
            }
#pragma unroll
            for (int nt = 0; nt < 8; ++nt) {
                int n = wn + nt * 8 + grp;
                uint32_t b0 = Ws[(kk + tig)     * 128 + n];
                uint32_t b1 = Ws[(kk + tig + 4) * 128 + n];
                mma_tf32(acc[0][nt], af[0][0], af[0][1], af[0][2], af[0][3], b0, b1);
                mma_tf32(acc[1][nt], af[1][0], af[1][1], af[1][2], af[1][3], b0, b1);
            }
        }
    }

#pragma unroll
    for (int mt = 0; mt < 2; ++mt) {
        int r0g = rowBase + wr + mt * 16 + grp;
        int r1g = r0g + 8;
#pragma unroll
        for (int nt = 0; nt < 8; ++nt) {
            int col = wn + nt * 8 + 2 * tig;
            float2 bv = *(const float2*)&bias[col];
            if (r0g < M) {
                float2 v;
                v.x = fmaxf(acc[mt][nt][0] + bv.x, 0.0f);
                v.y = fmaxf(acc[mt][nt][1] + bv.y, 0.0f);
                *(float2*)&C[(size_t)r0g * K_DIM + col] = v;
                __nv_bfloat162 hb = __floats2bfloat162_rn(v.x, v.y);
                *(__nv_bfloat162*)&Cb[(size_t)r0g * K_DIM + col] = hb;
            }
            if (r1g < M) {
                float2 v;
                v.x = fmaxf(acc[mt][nt][2] + bv.x, 0.0f);
                v.y = fmaxf(acc[mt][nt][3] + bv.y, 0.0f);
                *(float2*)&C[(size_t)r1g * K_DIM + col] = v;
                __nv_bfloat162 hb = __floats2bfloat162_rn(v.x, v.y);
                *(__nv_bfloat162*)&Cb[(size_t)r1g * K_DIM + col] = hb;
            }
        }
    }
}

// ---------------------------------------------------------------------------
// 5) fused SpMM2 + per-graph accumulation: one warp owns 32 consecutive
//    (graph-sorted) nodes; accumulates sum(h1) and sum(agg(h1)) in registers,
//    flushing spread atomics at graph boundaries.  No agg materialization.
__global__ void k_spmm_gs(const __nv_bfloat16* __restrict__ X,
                          const float* __restrict__ H,
                          const int* __restrict__ gid) {
    int wglob = (blockIdx.x * blockDim.x + threadIdx.x) >> 5;
    int lane = threadIdx.x & 31;
    int ns = wglob * 32;
    if (ns >= K_NODES) return;
    int ne = ns + 32; if (ne > K_NODES) ne = K_NODES;

    int cur = gid[ns];
    float a1x = 0, a1y = 0, a1z = 0, a1w = 0;
    float a2x = 0, a2y = 0, a2z = 0, a2w = 0;
    int cnt = 0;

    for (int w = ns; w < ne; ++w) {
        int g = gid[w];
        if (g != cur) {
            float* p1 = &g_gs1[cur * K_DIM + lane * 4];
            atomicAdd(p1 + 0, a1x); atomicAdd(p1 + 1, a1y);
            atomicAdd(p1 + 2, a1z); atomicAdd(p1 + 3, a1w);
            float* p2 = &g_gs2[cur * K_DIM + lane * 4];
            atomicAdd(p2 + 0, a2x); atomicAdd(p2 + 1, a2y);
            atomicAdd(p2 + 2, a2z); atomicAdd(p2 + 3, a2w);
            if (lane == 0) atomicAdd(&g_gcnt[cur], cnt);
            a1x = a1y = a1z = a1w = 0;
            a2x = a2y = a2z = a2w = 0;
            cnt = 0; cur = g;
        }
        int e0 = g_rowptr[w], e1 = g_rowptr[w + 1];
        float sx = 0, sy = 0, sz = 0, sw = 0;
        gather_row(X, e0, e1, lane, sx, sy, sz, sw);
        float inv = (e1 > e0) ? 1.0f / (float)(e1 - e0) : 0.0f;
        a2x += sx * inv; a2y += sy * inv; a2z += sz * inv; a2w += sw * inv;
        float4 hv = *((const float4*)(H + (size_t)w * K_DIM) + lane);
        a1x += hv.x; a1y += hv.y; a1z += hv.z; a1w += hv.w;
        ++cnt;
    }
    float* p1 = &g_gs1[cur * K_DIM + lane * 4];
    atomicAdd(p1 + 0, a1x); atomicAdd(p1 + 1, a1y);
    atomicAdd(p1 + 2, a1z); atomicAdd(p1 + 3, a1w);
    float* p2 = &g_gs2[cur * K_DIM + lane * 4];
    atomicAdd(p2 + 0, a2x); atomicAdd(p2 + 1, a2y);
    atomicAdd(p2 + 2, a2z); atomicAdd(p2 + 3, a2w);
    if (lane == 0) atomicAdd(&g_gcnt[cur], cnt);
}

// ---------------------------------------------------------------------------
// 6) fused: hg = (gs1@W2s + gs2@W2n)/cnt + b2 ; out = [hg|perm]@Wc + bc
//    Also re-zeroes gs1/gs2/gcnt for the next kernel_launch call.
__global__ void k_hgcls(const float* __restrict__ W2s, const float* __restrict__ W2n,
                        const float* __restrict__ b2,
                        const float* __restrict__ perm,
                        const float* __restrict__ Wc,
                        const float* __restrict__ bc,
                        float* __restrict__ out) {
    __shared__ float s1[K_DIM], s2[K_DIM], hgs[K_DIM];
    __shared__ float red[K_CLS];
    __shared__ int scnt;
    int g = blockIdx.x, d = threadIdx.x;
    s1[d] = g_gs1[g * K_DIM + d];
    s2[d] = g_gs2[g * K_DIM + d];
    if (d == 0) scnt = g_gcnt[g];
    if (d < K_CLS) red[d] = bc[d];
    __syncthreads();
    // re-zero for next call (zero-invariant)
    g_gs1[g * K_DIM + d] = 0.0f;
    g_gs2[g * K_DIM + d] = 0.0f;
    if (d == 0) g_gcnt[g] = 0;
    float acc = 0.0f;
#pragma unroll 4
    for (int k = 0; k < K_DIM; ++k)
        acc += s1[k] * W2s[k * K_DIM + d] + s2[k] * W2n[k * K_DIM + d];
    int cnt = scnt;
    float inv = 1.0f / (float)(cnt > 1 ? cnt : 1);
    hgs[d] = acc * inv + b2[d];
    __syncthreads();
    if (d < 64) {
        int c = d & 7, seg = d >> 3;
        int k0 = seg * 32;
        float p = 0.0f;
#pragma unroll 4
        for (int k = k0; k < k0 + 32; ++k) {
            float val = (k < K_DIM) ? hgs[k] : perm[g * K_DIM + (k - K_DIM)];
            p += val * Wc[k * K_CLS + c];
        }
        atomicAdd(&red[c], p);
    }
    __syncthreads();
    if (d < K_CLS) out[g * K_CLS + d] = red[d];
}

// ---------------------------------------------------------------------------
extern "C" void kernel_launch(void* const* d_in, const int* in_sizes, int n_in,
                              void* d_out, int out_size) {
    const float* h    = (const float*)d_in[0];
    const float* perm = (const float*)d_in[1];
    const int*   src  = (const int*)  d_in[2];
    const int*   dst  = (const int*)  d_in[3];
    const int*   gid  = (const int*)  d_in[4];
    const float* W1s  = (const float*)d_in[5];
    const float* W1n  = (const float*)d_in[6];
    const float* b1   = (const float*)d_in[7];
    const float* W2s  = (const float*)d_in[8];
    const float* W2n  = (const float*)d_in[9];
    const float* b2   = (const float*)d_in[10];
    const float* Wc   = (const float*)d_in[11];
    const float* bc   = (const float*)d_in[12];
    float* out = (float*)d_out;
    (void)in_sizes; (void)n_in; (void)out_size;

    float* meanb;           cudaGetSymbolAddress((void**)&meanb, g_mean);
    float* h1b;             cudaGetSymbolAddress((void**)&h1b,   g_h1);
    __nv_bfloat16* hbb;     cudaGetSymbolAddress((void**)&hbb,   g_hb);
    __nv_bfloat16* h1bb;    cudaGetSymbolAddress((void**)&h1bb,  g_h1b);

    // CSR build (3 launches)
    k_prep<<<(K_QUADS + 255) / 256, 256>>>(h, hbb, dst);
    k_scan<<<K_NB, 256>>>();
    k_fill<<<(K_EDGES + 255) / 256, 256>>>(src, dst);

    int spmmBlocks = (K_NODES * 32 + 255) / 256;
    int gemmBlocks = (K_NODES + 127) / 128;
    int gsBlocks   = ((K_NODES + 31) / 32 * 32 + 255) / 256;

    // layer 1
    k_spmm_bf16<<<spmmBlocks, 256>>>(hbb, meanb);
    k_gemm_mma<<<gemmBlocks, 256>>>(h, meanb, W1s, W1n, b1, h1b, h1bb, K_NODES);

    // layer 2 on graph means: fused SpMM2 + per-graph sums, then readout
    k_spmm_gs<<<gsBlocks, 256>>>(h1bb, h1b, gid);
    k_hgcls<<<K_GRAPHS, K_DIM>>>(W2s, W2n, b2, perm, Wc, bc, out);
}

// round 10
// speedup vs baseline: 1.1815x; 1.1815x over previous
#include <cuda_runtime.h>
#include <cuda_bf16.h>
#include <cstdint>
#include <cstring>

// ---------------------------------------------------------------------------
// GraphSAGE (2-layer, mean agg) + graph-mean readout + linear classifier.
// R10: revert R9's over-fused SpMM2 (parallelism collapse) back to R7's
// warp-per-node SpMM + block-segmented graph accum.  Keep R9's fused prep
// and fixed lookback scan.  New: uint4 two-edges-per-load SpMM (issue-bound
// kernel -> fewer instructions per edge).
// ---------------------------------------------------------------------------

#define K_NODES  100000
#define K_EDGES  1600000
#define K_GRAPHS 64
#define K_DIM    128
#define K_CLS    8
#define K_NB     98            // ceil(100000/1024)
#define K_QUADS  (K_NODES * K_DIM / 4)

// scratch (static device memory; no allocations)
__device__ int   g_count [K_NODES];            // zero-invariant
__device__ int   g_rowptr[K_NODES + 1];
__device__ int   g_cursor[K_NODES];
__device__ int   g_esrc  [K_EDGES];
__device__ unsigned long long g_state[K_NB];   // packed (flag<<32)|value
__device__ float g_gs1   [K_GRAPHS * K_DIM];   // zero-invariant
__device__ float g_gs2   [K_GRAPHS * K_DIM];   // zero-invariant
__device__ int   g_gcnt  [K_GRAPHS];           // zero-invariant
__device__ float g_mean  [(size_t)K_NODES * K_DIM];
__device__ float g_h1    [(size_t)K_NODES * K_DIM];
__device__ __nv_bfloat16 g_hb  [(size_t)K_NODES * K_DIM];
__device__ __nv_bfloat16 g_h1b [(size_t)K_NODES * K_DIM];

// ---------------------------------------------------------------------------
// 0) prep: bf16 shadow of h + dst histogram (counts start zero) + state reset
__global__ void k_prep(const float* __restrict__ X, __nv_bfloat16* __restrict__ Y,
                       const int* __restrict__ dst) {
    int i = blockIdx.x * blockDim.x + threadIdx.x;
    if (i < K_NB) g_state[i] = 0ull;
    if (i < K_QUADS) {
        float4 v = *((const float4*)X + i);
        __nv_bfloat162 a = __floats2bfloat162_rn(v.x, v.y);
        __nv_bfloat162 b = __floats2bfloat162_rn(v.z, v.w);
        uint2 u;
        memcpy(&u.x, &a, 4);
        memcpy(&u.y, &b, 4);
        *((uint2*)Y + i) = u;
    }
    if (i < K_EDGES) atomicAdd(&g_count[dst[i]], 1);
}

// 1) single-pass scan (decoupled lookback, packed flag|value) -> rowptr,cursor
__global__ void k_scan() {
    __shared__ int sm[256];
    __shared__ int sExcl;
    int b = blockIdx.x, t = threadIdx.x;
    int base = b * 1024 + t * 4;
    int c[4];
    int s = 0;
#pragma unroll
    for (int j = 0; j < 4; ++j) {
        int i = base + j;
        c[j] = (i < K_NODES) ? g_count[i] : 0;
        if (i < K_NODES) g_count[i] = 0;       // maintain zero-invariant
        s += c[j];
    }
    sm[t] = s;
    __syncthreads();
    for (int o = 1; o < 256; o <<= 1) {
        int u = (t >= o) ? sm[t - o] : 0;
        __syncthreads();
        sm[t] += u;
        __syncthreads();
    }
    int S = sm[255];
    if (t == 0) {
        if (b == 0) {
            atomicExch(&g_state[0], (2ull << 32) | (unsigned int)S);
            sExcl = 0;
        } else {
            atomicExch(&g_state[b], (1ull << 32) | (unsigned int)S);
            int excl = 0, p = b - 1;
            while (true) {
                unsigned long long v = atomicAdd(&g_state[p], 0ull);
                unsigned int f = (unsigned int)(v >> 32);
                if (f == 0) continue;
                excl += (int)(unsigned int)v;
                if (f == 2) break;
                --p;
            }
            atomicExch(&g_state[b], (2ull << 32) | (unsigned int)(excl + S));
            sExcl = excl;
        }
    }
    __syncthreads();
    int off = sExcl + sm[t] - s;
#pragma unroll
    for (int j = 0; j < 4; ++j) {
        int i = base + j;
        if (i < K_NODES) {
            g_rowptr[i] = off;
            g_cursor[i] = off;
        }
        off += c[j];
    }
    if (b == K_NB - 1 && t == 255) g_rowptr[K_NODES] = sExcl + S;
}

// 2) bucket fill: sort edge srcs by dst
__global__ void k_fill(const int* __restrict__ src, const int* __restrict__ dst) {
    int i = blockIdx.x * blockDim.x + threadIdx.x;
    if (i < K_EDGES) {
        int p = atomicAdd(&g_cursor[dst[i]], 1);
        g_esrc[p] = src[i];
    }
}

// ---------------------------------------------------------------------------
// 3) SpMM mean: warp per dst row; lanes 0-15 / 16-31 take alternating edges,
//    each lane loads uint4 (8 bf16 dims) per edge; exact shift/mask bf16->f32;
//    cross-half shfl reduce at the end.
__device__ __forceinline__ void acc8(uint4 u, float* a) {
    a[0] += __uint_as_float(u.x << 16);
    a[1] += __uint_as_float(u.x & 0xFFFF0000u);
    a[2] += __uint_as_float(u.y << 16);
    a[3] += __uint_as_float(u.y & 0xFFFF0000u);
    a[4] += __uint_as_float(u.z << 16);
    a[5] += __uint_as_float(u.z & 0xFFFF0000u);
    a[6] += __uint_as_float(u.w << 16);
    a[7] += __uint_as_float(u.w & 0xFFFF0000u);
}

__global__ void k_spmm_bf16(const __nv_bfloat16* __restrict__ X, float* __restrict__ Y) {
    int w = (blockIdx.x * blockDim.x + threadIdx.x) >> 5;
    int lane = threadIdx.x & 31;
    if (w >= K_NODES) return;
    int e0 = g_rowptr[w], e1 = g_rowptr[w + 1];
    int half = lane >> 4, sub = lane & 15;
    const char* base = (const char*)X + sub * 16;     // 8 dims * 2B per lane

    float a[8];
#pragma unroll
    for (int j = 0; j < 8; ++j) a[j] = 0.0f;

    int e = e0;
    for (; e + 8 <= e1; e += 8) {                     // 4 edge-pairs per iter
        int s[4];
#pragma unroll
        for (int q = 0; q < 4; ++q) s[q] = g_esrc[e + 2 * q + half];
        uint4 u[4];
#pragma unroll
        for (int q = 0; q < 4; ++q)
            u[q] = *(const uint4*)(base + (size_t)s[q] * 256);
#pragma unroll
        for (int q = 0; q < 4; ++q) acc8(u[q], a);
    }
    for (; e + 2 <= e1; e += 2) {
        int s = g_esrc[e + half];
        uint4 u = *(const uint4*)(base + (size_t)s * 256);
        acc8(u, a);
    }
    if (e < e1 && half == 0) {                        // odd tail edge
        int s = g_esrc[e];
        uint4 u = *(const uint4*)(base + (size_t)s * 256);
        acc8(u, a);
    }
    // combine the two edge-halves
#pragma unroll
    for (int j = 0; j < 8; ++j)
        a[j] += __shfl_xor_sync(0xffffffffu, a[j], 16);

    float inv = (e1 > e0) ? 1.0f / (float)(e1 - e0) : 0.0f;
    float4 r;
    int jb = half * 4;
    r.x = a[jb + 0] * inv; r.y = a[jb + 1] * inv;
    r.z = a[jb + 2] * inv; r.w = a[jb + 3] * inv;
    *((float4*)(Y + (size_t)w * K_DIM + sub * 8 + half * 4)) = r;
}

// ---------------------------------------------------------------------------
// 4) mma.sync tf32 dual GEMM with register-prefetch double buffering.
__device__ __forceinline__ uint32_t f2tf32(float x) {
    uint32_t u;
    asm("cvt.rna.tf32.f32 %0, %1;" : "=r"(u) : "f"(x));
    return u;
}
__device__ __forceinline__ void mma_tf32(float* c, uint32_t a0, uint32_t a1,
                                         uint32_t a2, uint32_t a3,
                                         uint32_t b0, uint32_t b1) {
    asm volatile(
        "mma.sync.aligned.m16n8k8.row.col.f32.tf32.tf32.f32 "
        "{%0,%1,%2,%3}, {%4,%5,%6,%7}, {%8,%9}, {%0,%1,%2,%3};"
        : "+f"(c[0]), "+f"(c[1]), "+f"(c[2]), "+f"(c[3])
        : "r"(a0), "r"(a1), "r"(a2), "r"(a3), "r"(b0), "r"(b1));
}

__global__ __launch_bounds__(256, 2)
void k_gemm_mma(const float* __restrict__ A1, const float* __restrict__ A2,
                const float* __restrict__ W1, const float* __restrict__ W2,
                const float* __restrict__ bias, float* __restrict__ C,
                __nv_bfloat16* __restrict__ Cb, int M) {
    __shared__ __align__(16) uint32_t Xs[32 * 132];
    __shared__ __align__(16) uint32_t Ws[32 * 128];
    int tid = threadIdx.x, wid = tid >> 5, lane = tid & 31;
    int grp = lane >> 2, tig = lane & 3;
    int warpM = wid & 3, warpN = wid >> 2;
    int rowBase = blockIdx.x * 128;
    int wr = warpM * 32;
    int wn = warpN * 64;

    int rloc = tid >> 3;
    int kq   = (tid & 7) << 2;
    int wkk  = tid >> 5;
    int wnn  = (tid & 31) << 2;

    float acc[2][8][4];
#pragma unroll
    for (int mt = 0; mt < 2; ++mt)
#pragma unroll
        for (int nt = 0; nt < 8; ++nt)
#pragma unroll
            for (int q = 0; q < 4; ++q) acc[mt][nt][q] = 0.0f;

    float4 ra[4], rw[4];
    {
#pragma unroll
        for (int i = 0; i < 4; ++i) {
            int grow = rowBase + rloc + i * 32; if (grow >= M) grow = M - 1;
            ra[i] = *(const float4*)&A1[(size_t)grow * K_DIM + kq];
        }
#pragma unroll
        for (int i = 0; i < 4; ++i) {
            int kk = wkk + i * 8;
            rw[i] = *(const float4*)&W1[(size_t)kk * K_DIM + wnn];
        }
    }

#pragma unroll 1
    for (int cc = 0; cc < 8; ++cc) {
        __syncthreads();
#pragma unroll
        for (int i = 0; i < 4; ++i) {
            int rr = rloc + i * 32;
            Xs[(kq + 0) * 132 + rr] = f2tf32(ra[i].x);
            Xs[(kq + 1) * 132 + rr] = f2tf32(ra[i].y);
            Xs[(kq + 2) * 132 + rr] = f2tf32(ra[i].z);
            Xs[(kq + 3) * 132 + rr] = f2tf32(ra[i].w);
        }
#pragma unroll
        for (int i = 0; i < 4; ++i) {
            int kk = wkk + i * 8;
            Ws[kk * 128 + wnn + 0] = f2tf32(rw[i].x);
            Ws[kk * 128 + wnn + 1] = f2tf32(rw[i].y);
            Ws[kk * 128 + wnn + 2] = f2tf32(rw[i].z);
            Ws[kk * 128 + wnn + 3] = f2tf32(rw[i].w);
        }
        __syncthreads();
        if (cc < 7) {
            int nc = cc + 1;
            const float* A = (nc >= 4) ? A2 : A1;
            const float* W = (nc >= 4) ? W2 : W1;
            int k0 = (nc & 3) * 32;
#pragma unroll
            for (int i = 0; i < 4; ++i) {
                int grow = rowBase + rloc + i * 32; if (grow >= M) grow = M - 1;
                ra[i] = *(const float4*)&A[(size_t)grow * K_DIM + k0 + kq];
            }
#pragma unroll
            for (int i = 0; i < 4; ++i) {
                int kk = wkk + i * 8;
                rw[i] = *(const float4*)&W[(size_t)(k0 + kk) * K_DIM + wnn];
            }
        }
#pragma unroll
        for (int ks = 0; ks < 4; ++ks) {
            int kk = ks * 8;
            uint32_t af[2][4];
#pragma unroll
            for (int mt = 0; mt < 2; ++mt) {
                int r = wr + mt * 16 + grp;
                af[mt][0] = Xs[(kk + tig)     * 132 + r];
                af[mt][1] = Xs[(kk + tig)     * 132 + r + 8];
                af[mt][2] = Xs[(kk + tig + 4) * 132 + r];
                af[mt][3] = Xs[(kk + tig + 4) * 132 + r + 8];
            }
#pragma unroll
            for (int nt = 0; nt < 8; ++nt) {
                int n = wn + nt * 8 + grp;
                uint32_t b0 = Ws[(kk + tig)     * 128 + n];
                uint32_t b1 = Ws[(kk + tig + 4) * 128 + n];
                mma_tf32(acc[0][nt], af[0][0], af[0][1], af[0][2], af[0][3], b0, b1);
                mma_tf32(acc[1][nt], af[1][0], af[1][1], af[1][2], af[1][3], b0, b1);
            }
        }
    }

#pragma unroll
    for (int mt = 0; mt < 2; ++mt) {
        int r0g = rowBase + wr + mt * 16 + grp;
        int r1g = r0g + 8;
#pragma unroll
        for (int nt = 0; nt < 8; ++nt) {
            int col = wn + nt * 8 + 2 * tig;
            float2 bv = *(const float2*)&bias[col];
            if (r0g < M) {
                float2 v;
                v.x = fmaxf(acc[mt][nt][0] + bv.x, 0.0f);
                v.y = fmaxf(acc[mt][nt][1] + bv.y, 0.0f);
                *(float2*)&C[(size_t)r0g * K_DIM + col] = v;
                __nv_bfloat162 hb = __floats2bfloat162_rn(v.x, v.y);
                *(__nv_bfloat162*)&Cb[(size_t)r0g * K_DIM + col] = hb;
            }
            if (r1g < M) {
                float2 v;
                v.x = fmaxf(acc[mt][nt][2] + bv.x, 0.0f);
                v.y = fmaxf(acc[mt][nt][3] + bv.y, 0.0f);
                *(float2*)&C[(size_t)r1g * K_DIM + col] = v;
                __nv_bfloat162 hb = __floats2bfloat162_rn(v.x, v.y);
                *(__nv_bfloat162*)&Cb[(size_t)r1g * K_DIM + col] = hb;
            }
        }
    }
}

// ---------------------------------------------------------------------------
// 5) fused per-graph sums of h1 AND agg(h1): segmented register accumulation
__global__ void k_graph_accum2(const float* __restrict__ H,
                               const float* __restrict__ Agg,
                               const int* __restrict__ gid) {
    int c = threadIdx.x;                 // 128 threads = one dim each
    int rs = blockIdx.x * 64;
    if (rs >= K_NODES) return;
    int re = rs + 64;
    if (re > K_NODES) re = K_NODES;
    int cur = gid[rs];
    float a1 = 0.0f, a2 = 0.0f;
    int cnt = 0;
    for (int r = rs; r < re; ++r) {
        int g = gid[r];
        if (g != cur) {
            atomicAdd(&g_gs1[cur * K_DIM + c], a1);
            atomicAdd(&g_gs2[cur * K_DIM + c], a2);
            if (c == 0) atomicAdd(&g_gcnt[cur], cnt);
            a1 = 0.0f; a2 = 0.0f; cnt = 0; cur = g;
        }
        a1 += H  [(size_t)r * K_DIM + c];
        a2 += Agg[(size_t)r * K_DIM + c];
        ++cnt;
    }
    atomicAdd(&g_gs1[cur * K_DIM + c], a1);
    atomicAdd(&g_gs2[cur * K_DIM + c], a2);
    if (c == 0) atomicAdd(&g_gcnt[cur], cnt);
}

// ---------------------------------------------------------------------------
// 6) fused: hg = (gs1@W2s + gs2@W2n)/cnt + b2 ; out = [hg|perm]@Wc + bc
//    Re-zeroes gs1/gs2/gcnt for the next kernel_launch call.
__global__ void k_hgcls(const float* __restrict__ W2s, const float* __restrict__ W2n,
                        const float* __restrict__ b2,
                        const float* __restrict__ perm,
                        const float* __restrict__ Wc,
                        const float* __restrict__ bc,
                        float* __restrict__ out) {
    __shared__ float s1[K_DIM], s2[K_DIM], hgs[K_DIM];
    __shared__ float red[K_CLS];
    __shared__ int scnt;
    int g = blockIdx.x, d = threadIdx.x;
    s1[d] = g_gs1[g * K_DIM + d];
    s2[d] = g_gs2[g * K_DIM + d];
    if (d == 0) scnt = g_gcnt[g];
    if (d < K_CLS) red[d] = bc[d];
    __syncthreads();
    g_gs1[g * K_DIM + d] = 0.0f;       // zero-invariant for next call
    g_gs2[g * K_DIM + d] = 0.0f;
    if (d == 0) g_gcnt[g] = 0;
    float acc = 0.0f;
#pragma unroll 4
    for (int k = 0; k < K_DIM; ++k)
        acc += s1[k] * W2s[k * K_DIM + d] + s2[k] * W2n[k * K_DIM + d];
    int cnt = scnt;
    float inv = 1.0f / (float)(cnt > 1 ? cnt : 1);
    hgs[d] = acc * inv + b2[d];
    __syncthreads();
    if (d < 64) {
        int c = d & 7, seg = d >> 3;
        int k0 = seg * 32;
        float p = 0.0f;
#pragma unroll 4
        for (int k = k0; k < k0 + 32; ++k) {
            float val = (k < K_DIM) ? hgs[k] : perm[g * K_DIM + (k - K_DIM)];
            p += val * Wc[k * K_CLS + c];
        }
        atomicAdd(&red[c], p);
    }
    __syncthreads();
    if (d < K_CLS) out[g * K_CLS + d] = red[d];
}

// ---------------------------------------------------------------------------
extern "C" void kernel_launch(void* const* d_in, const int* in_sizes, int n_in,
                              void* d_out, int out_size) {
    const float* h    = (const float*)d_in[0];
    const float* perm = (const float*)d_in[1];
    const int*   src  = (const int*)  d_in[2];
    const int*   dst  = (const int*)  d_in[3];
    const int*   gid  = (const int*)  d_in[4];
    const float* W1s  = (const float*)d_in[5];
    const float* W1n  = (const float*)d_in[6];
    const float* b1   = (const float*)d_in[7];
    const float* W2s  = (const float*)d_in[8];
    const float* W2n  = (const float*)d_in[9];
    const float* b2   = (const float*)d_in[10];
    const float* Wc   = (const float*)d_in[11];
    const float* bc   = (const float*)d_in[12];
    float* out = (float*)d_out;
    (void)in_sizes; (void)n_in; (void)out_size;

    float* meanb;           cudaGetSymbolAddress((void**)&meanb, g_mean);
    float* h1b;             cudaGetSymbolAddress((void**)&h1b,   g_h1);
    __nv_bfloat16* hbb;     cudaGetSymbolAddress((void**)&hbb,   g_hb);
    __nv_bfloat16* h1bb;    cudaGetSymbolAddress((void**)&h1bb,  g_h1b);

    // CSR build (3 launches)
    k_prep<<<(K_QUADS + 255) / 256, 256>>>(h, hbb, dst);
    k_scan<<<K_NB, 256>>>();
    k_fill<<<(K_EDGES + 255) / 256, 256>>>(src, dst);

    int spmmBlocks = (K_NODES * 32 + 255) / 256;
    int gemmBlocks = (K_NODES + 127) / 128;

    // layer 1
    k_spmm_bf16<<<spmmBlocks, 256>>>(hbb, meanb);
    k_gemm_mma<<<gemmBlocks, 256>>>(h, meanb, W1s, W1n, b1, h1b, h1bb, K_NODES);

    // layer 2 on graph means (linearity of mean-pool):
    k_spmm_bf16<<<spmmBlocks, 256>>>(h1bb, meanb);               // agg(h1)
    k_graph_accum2<<<(K_NODES + 63) / 64, 128>>>(h1b, meanb, gid);
    k_hgcls<<<K_GRAPHS, K_DIM>>>(W2s, W2n, b2, perm, Wc, bc, out);
}

// round 11
// speedup vs baseline: 1.3127x; 1.1110x over previous
#include <cuda_runtime.h>
#include <cuda_bf16.h>
#include <cstdint>
#include <cstring>

// ---------------------------------------------------------------------------
// GraphSAGE (2-layer, mean agg) + graph-mean readout + linear classifier.
// R11: bf16 m16n8k16 GEMM (bf16 A operands straight from shadows, halved LDS
// and MMA count); SpMM1 writes bf16 mean only; SpMM2 fused with block-level
// segmented graph reduction (warp-per-node parallelism kept). 7 launches.
// ---------------------------------------------------------------------------

#define K_NODES  100000
#define K_EDGES  1600000
#define K_GRAPHS 64
#define K_DIM    128
#define K_CLS    8
#define K_NB     98            // ceil(100000/1024)
#define K_QUADS  (K_NODES * K_DIM / 4)

// scratch (static device memory; no allocations)
__device__ int   g_count [K_NODES];            // zero-invariant
__device__ int   g_rowptr[K_NODES + 1];
__device__ int   g_cursor[K_NODES];
__device__ int   g_esrc  [K_EDGES];
__device__ unsigned long long g_state[K_NB];   // packed (flag<<32)|value
__device__ float g_gs1   [K_GRAPHS * K_DIM];   // zero-invariant
__device__ float g_gs2   [K_GRAPHS * K_DIM];   // zero-invariant
__device__ int   g_gcnt  [K_GRAPHS];           // zero-invariant
__device__ float g_h1    [(size_t)K_NODES * K_DIM];
__device__ __nv_bfloat16 g_hb  [(size_t)K_NODES * K_DIM];   // bf16 h
__device__ __nv_bfloat16 g_mb  [(size_t)K_NODES * K_DIM];   // bf16 mean
__device__ __nv_bfloat16 g_h1b [(size_t)K_NODES * K_DIM];   // bf16 h1

// ---------------------------------------------------------------------------
// 0) prep: bf16 shadow of h + dst histogram (counts start zero) + state reset
__global__ void k_prep(const float* __restrict__ X, __nv_bfloat16* __restrict__ Y,
                       const int* __restrict__ dst) {
    int i = blockIdx.x * blockDim.x + threadIdx.x;
    if (i < K_NB) g_state[i] = 0ull;
    if (i < K_QUADS) {
        float4 v = *((const float4*)X + i);
        __nv_bfloat162 a = __floats2bfloat162_rn(v.x, v.y);
        __nv_bfloat162 b = __floats2bfloat162_rn(v.z, v.w);
        uint2 u;
        memcpy(&u.x, &a, 4);
        memcpy(&u.y, &b, 4);
        *((uint2*)Y + i) = u;
    }
    if (i < K_EDGES) atomicAdd(&g_count[dst[i]], 1);
}

// 1) single-pass scan (decoupled lookback, packed flag|value) -> rowptr,cursor
__global__ void k_scan() {
    __shared__ int sm[256];
    __shared__ int sExcl;
    int b = blockIdx.x, t = threadIdx.x;
    int base = b * 1024 + t * 4;
    int c[4];
    int s = 0;
#pragma unroll
    for (int j = 0; j < 4; ++j) {
        int i = base + j;
        c[j] = (i < K_NODES) ? g_count[i] : 0;
        if (i < K_NODES) g_count[i] = 0;       // maintain zero-invariant
        s += c[j];
    }
    sm[t] = s;
    __syncthreads();
    for (int o = 1; o < 256; o <<= 1) {
        int u = (t >= o) ? sm[t - o] : 0;
        __syncthreads();
        sm[t] += u;
        __syncthreads();
    }
    int S = sm[255];
    if (t == 0) {
        if (b == 0) {
            atomicExch(&g_state[0], (2ull << 32) | (unsigned int)S);
            sExcl = 0;
        } else {
            atomicExch(&g_state[b], (1ull << 32) | (unsigned int)S);
            int excl = 0, p = b - 1;
            while (true) {
                unsigned long long v = atomicAdd(&g_state[p], 0ull);
                unsigned int f = (unsigned int)(v >> 32);
                if (f == 0) continue;
                excl += (int)(unsigned int)v;
                if (f == 2) break;
                --p;
            }
            atomicExch(&g_state[b], (2ull << 32) | (unsigned int)(excl + S));
            sExcl = excl;
        }
    }
    __syncthreads();
    int off = sExcl + sm[t] - s;
#pragma unroll
    for (int j = 0; j < 4; ++j) {
        int i = base + j;
        if (i < K_NODES) {
            g_rowptr[i] = off;
            g_cursor[i] = off;
        }
        off += c[j];
    }
    if (b == K_NB - 1 && t == 255) g_rowptr[K_NODES] = sExcl + S;
}

// 2) bucket fill: sort edge srcs by dst
__global__ void k_fill(const int* __restrict__ src, const int* __restrict__ dst) {
    int i = blockIdx.x * blockDim.x + threadIdx.x;
    if (i < K_EDGES) {
        int p = atomicAdd(&g_cursor[dst[i]], 1);
        g_esrc[p] = src[i];
    }
}

// ---------------------------------------------------------------------------
// gather core: warp per node, lanes 0-15/16-31 alternate edges, uint4 loads.
// result: a[8]; lane's final 4 dims are a[half*4..+3] at dim sub*8+half*4.
__device__ __forceinline__ void acc8(uint4 u, float* a) {
    a[0] += __uint_as_float(u.x << 16);
    a[1] += __uint_as_float(u.x & 0xFFFF0000u);
    a[2] += __uint_as_float(u.y << 16);
    a[3] += __uint_as_float(u.y & 0xFFFF0000u);
    a[4] += __uint_as_float(u.z << 16);
    a[5] += __uint_as_float(u.z & 0xFFFF0000u);
    a[6] += __uint_as_float(u.w << 16);
    a[7] += __uint_as_float(u.w & 0xFFFF0000u);
}

__device__ __forceinline__ void gather_node(const __nv_bfloat16* __restrict__ X,
                                            int e0, int e1, int half, int sub,
                                            float* a) {
    const char* base = (const char*)X + sub * 16;
#pragma unroll
    for (int j = 0; j < 8; ++j) a[j] = 0.0f;
    int e = e0;
    for (; e + 8 <= e1; e += 8) {
        int s[4];
#pragma unroll
        for (int q = 0; q < 4; ++q) s[q] = g_esrc[e + 2 * q + half];
        uint4 u[4];
#pragma unroll
        for (int q = 0; q < 4; ++q)
            u[q] = *(const uint4*)(base + (size_t)s[q] * 256);
#pragma unroll
        for (int q = 0; q < 4; ++q) acc8(u[q], a);
    }
    for (; e + 2 <= e1; e += 2) {
        int s = g_esrc[e + half];
        uint4 u = *(const uint4*)(base + (size_t)s * 256);
        acc8(u, a);
    }
    if (e < e1 && half == 0) {
        int s = g_esrc[e];
        uint4 u = *(const uint4*)(base + (size_t)s * 256);
        acc8(u, a);
    }
#pragma unroll
    for (int j = 0; j < 8; ++j)
        a[j] += __shfl_xor_sync(0xffffffffu, a[j], 16);
}

// 3) SpMM mean (layer 1): warp per node -> bf16 mean row
__global__ void k_spmm1(const __nv_bfloat16* __restrict__ X,
                        __nv_bfloat16* __restrict__ Y) {
    int w = (blockIdx.x * blockDim.x + threadIdx.x) >> 5;
    int lane = threadIdx.x & 31;
    if (w >= K_NODES) return;
    int e0 = g_rowptr[w], e1 = g_rowptr[w + 1];
    int half = lane >> 4, sub = lane & 15;
    float a[8];
    gather_node(X, e0, e1, half, sub, a);
    float inv = (e1 > e0) ? 1.0f / (float)(e1 - e0) : 0.0f;
    int jb = half * 4;
    __nv_bfloat162 p0 = __floats2bfloat162_rn(a[jb + 0] * inv, a[jb + 1] * inv);
    __nv_bfloat162 p1 = __floats2bfloat162_rn(a[jb + 2] * inv, a[jb + 3] * inv);
    uint2 st;
    memcpy(&st.x, &p0, 4);
    memcpy(&st.y, &p1, 4);
    *((uint2*)(Y + (size_t)w * K_DIM + sub * 8 + half * 4)) = st;
}

// ---------------------------------------------------------------------------
// 4) bf16 m16n8k16 dual GEMM: h1 = relu(A1@W1 + A2@W2 + bias)
//    A operands are bf16 (g_hb / g_mb); W converted fp32->bf16 in staging.
__device__ __forceinline__ void mma_bf16(float* c, uint32_t a0, uint32_t a1,
                                         uint32_t a2, uint32_t a3,
                                         uint32_t b0, uint32_t b1) {
    asm volatile(
        "mma.sync.aligned.m16n8k16.row.col.f32.bf16.bf16.f32 "
        "{%0,%1,%2,%3}, {%4,%5,%6,%7}, {%8,%9}, {%0,%1,%2,%3};"
        : "+f"(c[0]), "+f"(c[1]), "+f"(c[2]), "+f"(c[3])
        : "r"(a0), "r"(a1), "r"(a2), "r"(a3), "r"(b0), "r"(b1));
}

#define XPITCH 20   // words per 32-k row (16 data + 4 pad); mult of 4

__global__ __launch_bounds__(256, 2)
void k_gemm_bf16(const __nv_bfloat16* __restrict__ A1,
                 const __nv_bfloat16* __restrict__ A2,
                 const float* __restrict__ W1, const float* __restrict__ W2,
                 const float* __restrict__ bias, float* __restrict__ C,
                 __nv_bfloat16* __restrict__ Cb, int M) {
    __shared__ __align__(16) uint32_t Xs[128 * XPITCH];  // A tile, bf16 pairs
    __shared__ __align__(16) uint32_t Ws[128 * XPITCH];  // B tile [n][k] bf16 pairs
    int tid = threadIdx.x, wid = tid >> 5, lane = tid & 31;
    int grp = lane >> 2, tig = lane & 3;
    int warpM = wid & 3, warpN = wid >> 2;
    int rowBase = blockIdx.x * 128;
    int wr = warpM * 32;
    int wn = warpN * 64;

    // A staging coords: thread -> (row ar, 16-k half aq)
    int ar = tid >> 1, aq = tid & 1;
    // W staging coords
    int wkk = tid >> 5;              // base k row (step 8 over i)
    int wnn = (tid & 31) << 2;       // n quad

    float acc[2][8][4];
#pragma unroll
    for (int mt = 0; mt < 2; ++mt)
#pragma unroll
        for (int nt = 0; nt < 8; ++nt)
#pragma unroll
            for (int q = 0; q < 4; ++q) acc[mt][nt][q] = 0.0f;

    uint4 va[2];
    float4 rw[4];
    {
        int grow = rowBase + ar; if (grow >= M) grow = M - 1;
        const uint4* ap = (const uint4*)(A1 + (size_t)grow * K_DIM + aq * 16);
        va[0] = ap[0];
        va[1] = ap[1];
#pragma unroll
        for (int i = 0; i < 4; ++i) {
            int kk = wkk + i * 8;
            rw[i] = *(const float4*)&W1[(size_t)kk * K_DIM + wnn];
        }
    }

#pragma unroll 1
    for (int cc = 0; cc < 8; ++cc) {
        __syncthreads();
        // store A regs -> smem (raw bf16 copy)
        {
            int base = ar * XPITCH + aq * 8;
            *(uint4*)&Xs[base] = va[0];
            *(uint4*)&Xs[base + 4] = va[1];
        }
        // store W regs -> smem transposed [n][k], fp32 -> bf16
        {
            __nv_bfloat16* WB = (__nv_bfloat16*)Ws;
#pragma unroll
            for (int i = 0; i < 4; ++i) {
                int kk = wkk + i * 8;
                WB[(wnn + 0) * (2 * XPITCH) + kk] = __float2bfloat16(rw[i].x);
                WB[(wnn + 1) * (2 * XPITCH) + kk] = __float2bfloat16(rw[i].y);
                WB[(wnn + 2) * (2 * XPITCH) + kk] = __float2bfloat16(rw[i].z);
                WB[(wnn + 3) * (2 * XPITCH) + kk] = __float2bfloat16(rw[i].w);
            }
        }
        __syncthreads();
        // prefetch next chunk
        if (cc < 7) {
            int nc = cc + 1;
            const __nv_bfloat16* A = (nc >= 4) ? A2 : A1;
            const float* W = (nc >= 4) ? W2 : W1;
            int k0 = (nc & 3) * 32;
            int grow = rowBase + ar; if (grow >= M) grow = M - 1;
            const uint4* ap = (const uint4*)(A + (size_t)grow * K_DIM + k0 + aq * 16);
            va[0] = ap[0];
            va[1] = ap[1];
#pragma unroll
            for (int i = 0; i < 4; ++i) {
                int kk = wkk + i * 8;
                rw[i] = *(const float4*)&W[(size_t)(k0 + kk) * K_DIM + wnn];
            }
        }
        // mma mainloop: 2 k16 steps per 32-k chunk
#pragma unroll
        for (int ks = 0; ks < 2; ++ks) {
            int kw = ks * 8;
            uint32_t af[2][4];
#pragma unroll
            for (int mt = 0; mt < 2; ++mt) {
                int r = wr + mt * 16 + grp;
                af[mt][0] = Xs[r * XPITCH + kw + tig];
                af[mt][1] = Xs[(r + 8) * XPITCH + kw + tig];
                af[mt][2] = Xs[r * XPITCH + kw + tig + 4];
                af[mt][3] = Xs[(r + 8) * XPITCH + kw + tig + 4];
            }
#pragma unroll
            for (int nt = 0; nt < 8; ++nt) {
                int n = wn + nt * 8 + grp;
                uint32_t b0 = Ws[n * XPITCH + kw + tig];
                uint32_t b1 = Ws[n * XPITCH + kw + tig + 4];
                mma_bf16(acc[0][nt], af[0][0], af[0][1], af[0][2], af[0][3], b0, b1);
                mma_bf16(acc[1][nt], af[1][0], af[1][1], af[1][2], af[1][3], b0, b1);
            }
        }
    }

    // epilogue: bias + ReLU; fp32 store + bf16 shadow store
#pragma unroll
    for (int mt = 0; mt < 2; ++mt) {
        int r0g = rowBase + wr + mt * 16 + grp;
        int r1g = r0g + 8;
#pragma unroll
        for (int nt = 0; nt < 8; ++nt) {
            int col = wn + nt * 8 + 2 * tig;
            float2 bv = *(const float2*)&bias[col];
            if (r0g < M) {
                float2 v;
                v.x = fmaxf(acc[mt][nt][0] + bv.x, 0.0f);
                v.y = fmaxf(acc[mt][nt][1] + bv.y, 0.0f);
                *(float2*)&C[(size_t)r0g * K_DIM + col] = v;
                __nv_bfloat162 hb = __floats2bfloat162_rn(v.x, v.y);
                *(__nv_bfloat162*)&Cb[(size_t)r0g * K_DIM + col] = hb;
            }
            if (r1g < M) {
                float2 v;
                v.x = fmaxf(acc[mt][nt][2] + bv.x, 0.0f);
                v.y = fmaxf(acc[mt][nt][3] + bv.y, 0.0f);
                *(float2*)&C[(size_t)r1g * K_DIM + col] = v;
                __nv_bfloat162 hb = __floats2bfloat162_rn(v.x, v.y);
                *(__nv_bfloat162*)&Cb[(size_t)r1g * K_DIM + col] = hb;
            }
        }
    }
}

// ---------------------------------------------------------------------------
// 5) fused SpMM2 + per-graph sums: block = 16 warps = 16 graph-sorted nodes.
//    Each warp gathers its node's neighbor-mean (parallel); block then does a
//    segmented reduction over the 16 rows and flushes spread atomics.
__global__ __launch_bounds__(512)
void k_spmm_gs2(const __nv_bfloat16* __restrict__ X,     // h1b
                const float* __restrict__ H,              // h1 fp32
                const int* __restrict__ gid) {
    __shared__ float smean[16][K_DIM];
    __shared__ float sh1[16][K_DIM];
    __shared__ int sg[16];
    int wid = threadIdx.x >> 5, lane = threadIdx.x & 31;
    int node = blockIdx.x * 16 + wid;                     // 100000 = 6250*16
    int e0 = g_rowptr[node], e1 = g_rowptr[node + 1];
    int half = lane >> 4, sub = lane & 15;
    float a[8];
    gather_node(X, e0, e1, half, sub, a);
    float inv = (e1 > e0) ? 1.0f / (float)(e1 - e0) : 0.0f;
    int jb = half * 4;
    float4 mv;
    mv.x = a[jb + 0] * inv; mv.y = a[jb + 1] * inv;
    mv.z = a[jb + 2] * inv; mv.w = a[jb + 3] * inv;
    *(float4*)&smean[wid][sub * 8 + half * 4] = mv;
    float4 hv = *((const float4*)(H + (size_t)node * K_DIM) + lane);
    *(float4*)&sh1[wid][lane * 4] = hv;
    if (lane == 0) sg[wid] = gid[node];
    __syncthreads();

    int t = threadIdx.x;
    if (t < 256) {
        int d = t & 127;
        float* dstArr = (t < 128) ? g_gs1 : g_gs2;
        int cur = sg[0];
        float acc = 0.0f;
#pragma unroll
        for (int w = 0; w < 16; ++w) {
            int g = sg[w];
            float v = (t < 128) ? sh1[w][d] : smean[w][d];
            if (g != cur) {
                atomicAdd(&dstArr[cur * K_DIM + d], acc);
                acc = 0.0f; cur = g;
            }
            acc += v;
        }
        atomicAdd(&dstArr[cur * K_DIM + d], acc);
    } else if (t == 256) {
        int cur = sg[0], c = 0;
#pragma unroll
        for (int w = 0; w < 16; ++w) {
            int g = sg[w];
            if (g != cur) { atomicAdd(&g_gcnt[cur], c); c = 0; cur = g; }
            ++c;
        }
        atomicAdd(&g_gcnt[cur], c);
    }
}

// ---------------------------------------------------------------------------
// 6) fused: hg = (gs1@W2s + gs2@W2n)/cnt + b2 ; out = [hg|perm]@Wc + bc
//    Re-zeroes gs1/gs2/gcnt for the next kernel_launch call.
__global__ void k_hgcls(const float* __restrict__ W2s, const float* __restrict__ W2n,
                        const float* __restrict__ b2,
                        const float* __restrict__ perm,
                        const float* __restrict__ Wc,
                        const float* __restrict__ bc,
                        float* __restrict__ out) {
    __shared__ float s1[K_DIM], s2[K_DIM], hgs[K_DIM];
    __shared__ float red[K_CLS];
    __shared__ int scnt;
    int g = blockIdx.x, d = threadIdx.x;
    s1[d] = g_gs1[g * K_DIM + d];
    s2[d] = g_gs2[g * K_DIM + d];
    if (d == 0) scnt = g_gcnt[g];
    if (d < K_CLS) red[d] = bc[d];
    __syncthreads();
    g_gs1[g * K_DIM + d] = 0.0f;       // zero-invariant for next call
    g_gs2[g * K_DIM + d] = 0.0f;
    if (d == 0) g_gcnt[g] = 0;
    float acc = 0.0f;
#pragma unroll 4
    for (int k = 0; k < K_DIM; ++k)
        acc += s1[k] * W2s[k * K_DIM + d] + s2[k] * W2n[k * K_DIM + d];
    int cnt = scnt;
    float inv = 1.0f / (float)(cnt > 1 ? cnt : 1);
    hgs[d] = acc * inv + b2[d];
    __syncthreads();
    if (d < 64) {
        int c = d & 7, seg = d >> 3;
        int k0 = seg * 32;
        float p = 0.0f;
#pragma unroll 4
        for (int k = k0; k < k0 + 32; ++k) {
            float val = (k < K_DIM) ? hgs[k] : perm[g * K_DIM + (k - K_DIM)];
            p += val * Wc[k * K_CLS + c];
        }
        atomicAdd(&red[c], p);
    }
    __syncthreads();
    if (d < K_CLS) out[g * K_CLS + d] = red[d];
}

// ---------------------------------------------------------------------------
extern "C" void kernel_launch(void* const* d_in, const int* in_sizes, int n_in,
                              void* d_out, int out_size) {
    const float* h    = (const float*)d_in[0];
    const float* perm = (const float*)d_in[1];
    const int*   src  = (const int*)  d_in[2];
    const int*   dst  = (const int*)  d_in[3];
    const int*   gid  = (const int*)  d_in[4];
    const float* W1s  = (const float*)d_in[5];
    const float* W1n  = (const float*)d_in[6];
    const float* b1   = (const float*)d_in[7];
    const float* W2s  = (const float*)d_in[8];
    const float* W2n  = (const float*)d_in[9];
    const float* b2   = (const float*)d_in[10];
    const float* Wc   = (const float*)d_in[11];
    const float* bc   = (const float*)d_in[12];
    float* out = (float*)d_out;
    (void)in_sizes; (void)n_in; (void)out_size;

    float* h1b;             cudaGetSymbolAddress((void**)&h1b,   g_h1);
    __nv_bfloat16* hbb;     cudaGetSymbolAddress((void**)&hbb,   g_hb);
    __nv_bfloat16* mbb;     cudaGetSymbolAddress((void**)&mbb,   g_mb);
    __nv_bfloat16* h1bb;    cudaGetSymbolAddress((void**)&h1bb,  g_h1b);

    // CSR build (3 launches)
    k_prep<<<(K_QUADS + 255) / 256, 256>>>(h, hbb, dst);
    k_scan<<<K_NB, 256>>>();
    k_fill<<<(K_EDGES + 255) / 256, 256>>>(src, dst);

    int spmmBlocks = (K_NODES * 32 + 255) / 256;
    int gemmBlocks = (K_NODES + 127) / 128;

    // layer 1
    k_spmm1<<<spmmBlocks, 256>>>(hbb, mbb);
    k_gemm_bf16<<<gemmBlocks, 256>>>(hbb, mbb, W1s, W1n, b1, h1b, h1bb, K_NODES);

    // layer 2 on graph means: fused SpMM2 + per-graph sums, then readout
    k_spmm_gs2<<<K_NODES / 16, 512>>>(h1bb, h1b, gid);
    k_hgcls<<<K_GRAPHS, K_DIM>>>(W2s, W2n, b2, perm, Wc, bc, out);
}

// round 12
// speedup vs baseline: 1.3587x; 1.0350x over previous
#include <cuda_runtime.h>
#include <cuda_bf16.h>
#include <cuda_fp16.h>
#include <cstdint>
#include <cstring>

// ---------------------------------------------------------------------------
// GraphSAGE (2-layer, mean agg) + graph-mean readout + linear classifier.
// R12: fp8(e4m3) shadows for BOTH neighbor-gather passes (half the gather
// bytes, decode via cvt.e4m3x2->f16x2 + HADD2); fp32 h1 stream eliminated
// (GEMM writes bf16+fp8 shadows only; gs1 sums the bf16 shadow).
// 7 launches.  bf16 m16n8k16 GEMM unchanged from R11.
// ---------------------------------------------------------------------------

#define K_NODES  100000
#define K_EDGES  1600000
#define K_GRAPHS 64
#define K_DIM    128
#define K_CLS    8
#define K_NB     98            // ceil(100000/1024)
#define K_QUADS  (K_NODES * K_DIM / 4)

// scratch (static device memory; no allocations)
__device__ int   g_count [K_NODES];            // zero-invariant
__device__ int   g_rowptr[K_NODES + 1];
__device__ int   g_cursor[K_NODES];
__device__ int   g_esrc  [K_EDGES];
__device__ unsigned long long g_state[K_NB];   // packed (flag<<32)|value
__device__ float g_gs1   [K_GRAPHS * K_DIM];   // zero-invariant
__device__ float g_gs2   [K_GRAPHS * K_DIM];   // zero-invariant
__device__ int   g_gcnt  [K_GRAPHS];           // zero-invariant
__device__ __nv_bfloat16 g_hb  [(size_t)K_NODES * K_DIM];   // bf16 h
__device__ __nv_bfloat16 g_mb  [(size_t)K_NODES * K_DIM];   // bf16 mean
__device__ __nv_bfloat16 g_h1b [(size_t)K_NODES * K_DIM];   // bf16 h1
__device__ uint8_t       g_h8  [(size_t)K_NODES * K_DIM];   // fp8 h
__device__ uint8_t       g_h18 [(size_t)K_NODES * K_DIM];   // fp8 h1

// ---------------------------------------------------------------------------
// 0) prep: bf16 + fp8 shadows of h + dst histogram + state reset
__global__ void k_prep(const float* __restrict__ X, __nv_bfloat16* __restrict__ Y,
                       uint8_t* __restrict__ Y8, const int* __restrict__ dst) {
    int i = blockIdx.x * blockDim.x + threadIdx.x;
    if (i < K_NB) g_state[i] = 0ull;
    if (i < K_QUADS) {
        float4 v = *((const float4*)X + i);
        __nv_bfloat162 a = __floats2bfloat162_rn(v.x, v.y);
        __nv_bfloat162 b = __floats2bfloat162_rn(v.z, v.w);
        uint2 u;
        memcpy(&u.x, &a, 4);
        memcpy(&u.y, &b, 4);
        *((uint2*)Y + i) = u;
        unsigned short p01, p23;
        asm("cvt.rn.satfinite.e4m3x2.f32 %0, %1, %2;" : "=h"(p01) : "f"(v.y), "f"(v.x));
        asm("cvt.rn.satfinite.e4m3x2.f32 %0, %1, %2;" : "=h"(p23) : "f"(v.w), "f"(v.z));
        ((uint32_t*)Y8)[i] = (uint32_t)p01 | ((uint32_t)p23 << 16);
    }
    if (i < K_EDGES) atomicAdd(&g_count[dst[i]], 1);
}

// 1) single-pass scan (decoupled lookback, packed flag|value) -> rowptr,cursor
__global__ void k_scan() {
    __shared__ int sm[256];
    __shared__ int sExcl;
    int b = blockIdx.x, t = threadIdx.x;
    int base = b * 1024 + t * 4;
    int c[4];
    int s = 0;
#pragma unroll
    for (int j = 0; j < 4; ++j) {
        int i = base + j;
        c[j] = (i < K_NODES) ? g_count[i] : 0;
        if (i < K_NODES) g_count[i] = 0;       // maintain zero-invariant
        s += c[j];
    }
    sm[t] = s;
    __syncthreads();
    for (int o = 1; o < 256; o <<= 1) {
        int u = (t >= o) ? sm[t - o] : 0;
        __syncthreads();
        sm[t] += u;
        __syncthreads();
    }
    int S = sm[255];
    if (t == 0) {
        if (b == 0) {
            atomicExch(&g_state[0], (2ull << 32) | (unsigned int)S);
            sExcl = 0;
        } else {
            atomicExch(&g_state[b], (1ull << 32) | (unsigned int)S);
            int excl = 0, p = b - 1;
            while (true) {
                unsigned long long v = atomicAdd(&g_state[p], 0ull);
                unsigned int f = (unsigned int)(v >> 32);
                if (f == 0) continue;
                excl += (int)(unsigned int)v;
                if (f == 2) break;
                --p;
            }
            atomicExch(&g_state[b], (2ull << 32) | (unsigned int)(excl + S));
            sExcl = excl;
        }
    }
    __syncthreads();
    int off = sExcl + sm[t] - s;
#pragma unroll
    for (int j = 0; j < 4; ++j) {
        int i = base + j;
        if (i < K_NODES) {
            g_rowptr[i] = off;
            g_cursor[i] = off;
        }
        off += c[j];
    }
    if (b == K_NB - 1 && t == 255) g_rowptr[K_NODES] = sExcl + S;
}

// 2) bucket fill: sort edge srcs by dst
__global__ void k_fill(const int* __restrict__ src, const int* __restrict__ dst) {
    int i = blockIdx.x * blockDim.x + threadIdx.x;
    if (i < K_EDGES) {
        int p = atomicAdd(&g_cursor[dst[i]], 1);
        g_esrc[p] = src[i];
    }
}

// ---------------------------------------------------------------------------
// fp8 gather core: warp per node, lanes 0-15/16-31 alternate edges.
// Each lane loads uint2 = 8 fp8 dims; decode e4m3x2->f16x2; HADD2 accumulate.
__device__ __forceinline__ void cvt8(uint32_t w, __half2& lo, __half2& hi) {
    uint32_t r0, r1;
    asm("cvt.rn.f16x2.e4m3x2 %0, %1;" : "=r"(r0) : "h"((unsigned short)(w & 0xFFFFu)));
    asm("cvt.rn.f16x2.e4m3x2 %0, %1;" : "=r"(r1) : "h"((unsigned short)(w >> 16)));
    memcpy(&lo, &r0, 4);
    memcpy(&hi, &r1, 4);
}
__device__ __forceinline__ void acc8f8(uint2 u, __half2* acc) {
    __half2 a0, a1, a2, a3;
    cvt8(u.x, a0, a1);
    cvt8(u.y, a2, a3);
    acc[0] = __hadd2(acc[0], a0);
    acc[1] = __hadd2(acc[1], a1);
    acc[2] = __hadd2(acc[2], a2);
    acc[3] = __hadd2(acc[3], a3);
}

// result: a[8] fp32 sums; lane's final 4 dims are a[half*4..+3] at dim sub*8+half*4
__device__ __forceinline__ void gather_node8(const uint8_t* __restrict__ X8,
                                             int e0, int e1, int half, int sub,
                                             float* a) {
    const char* base = (const char*)X8 + sub * 8;
    __half2 hacc[4];
    __half2 hz = __float2half2_rn(0.0f);
#pragma unroll
    for (int j = 0; j < 4; ++j) hacc[j] = hz;
    int e = e0;
    for (; e + 8 <= e1; e += 8) {
        int s[4];
#pragma unroll
        for (int q = 0; q < 4; ++q) s[q] = g_esrc[e + 2 * q + half];
        uint2 u[4];
#pragma unroll
        for (int q = 0; q < 4; ++q)
            u[q] = *(const uint2*)(base + (size_t)s[q] * 128);
#pragma unroll
        for (int q = 0; q < 4; ++q) acc8f8(u[q], hacc);
    }
    for (; e + 2 <= e1; e += 2) {
        int s = g_esrc[e + half];
        uint2 u = *(const uint2*)(base + (size_t)s * 128);
        acc8f8(u, hacc);
    }
    if (e < e1 && half == 0) {
        int s = g_esrc[e];
        uint2 u = *(const uint2*)(base + (size_t)s * 128);
        acc8f8(u, hacc);
    }
#pragma unroll
    for (int j = 0; j < 4; ++j) {
        float2 f = __half22float2(hacc[j]);
        a[2 * j] = f.x;
        a[2 * j + 1] = f.y;
    }
#pragma unroll
    for (int j = 0; j < 8; ++j)
        a[j] += __shfl_xor_sync(0xffffffffu, a[j], 16);
}

// 3) SpMM mean (layer 1): warp per node, fp8 gather -> bf16 mean row
__global__ void k_spmm1(const uint8_t* __restrict__ X8,
                        __nv_bfloat16* __restrict__ Y) {
    int w = (blockIdx.x * blockDim.x + threadIdx.x) >> 5;
    int lane = threadIdx.x & 31;
    if (w >= K_NODES) return;
    int e0 = g_rowptr[w], e1 = g_rowptr[w + 1];
    int half = lane >> 4, sub = lane & 15;
    float a[8];
    gather_node8(X8, e0, e1, half, sub, a);
    float inv = (e1 > e0) ? 1.0f / (float)(e1 - e0) : 0.0f;
    int jb = half * 4;
    __nv_bfloat162 p0 = __floats2bfloat162_rn(a[jb + 0] * inv, a[jb + 1] * inv);
    __nv_bfloat162 p1 = __floats2bfloat162_rn(a[jb + 2] * inv, a[jb + 3] * inv);
    uint2 st;
    memcpy(&st.x, &p0, 4);
    memcpy(&st.y, &p1, 4);
    *((uint2*)(Y + (size_t)w * K_DIM + sub * 8 + half * 4)) = st;
}

// ---------------------------------------------------------------------------
// 4) bf16 m16n8k16 dual GEMM: h1 = relu(A1@W1 + A2@W2 + bias)
//    Outputs: bf16 shadow (GEMM-free consumers) + fp8 shadow (layer-2 gather).
__device__ __forceinline__ void mma_bf16(float* c, uint32_t a0, uint32_t a1,
                                         uint32_t a2, uint32_t a3,
                                         uint32_t b0, uint32_t b1) {
    asm volatile(
        "mma.sync.aligned.m16n8k16.row.col.f32.bf16.bf16.f32 "
        "{%0,%1,%2,%3}, {%4,%5,%6,%7}, {%8,%9}, {%0,%1,%2,%3};"
        : "+f"(c[0]), "+f"(c[1]), "+f"(c[2]), "+f"(c[3])
        : "r"(a0), "r"(a1), "r"(a2), "r"(a3), "r"(b0), "r"(b1));
}

#define XPITCH 20   // words per 32-k row (16 data + 4 pad); mult of 4

__global__ __launch_bounds__(256, 2)
void k_gemm_bf16(const __nv_bfloat16* __restrict__ A1,
                 const __nv_bfloat16* __restrict__ A2,
                 const float* __restrict__ W1, const float* __restrict__ W2,
                 const float* __restrict__ bias,
                 __nv_bfloat16* __restrict__ Cb, uint8_t* __restrict__ C8, int M) {
    __shared__ __align__(16) uint32_t Xs[128 * XPITCH];
    __shared__ __align__(16) uint32_t Ws[128 * XPITCH];
    int tid = threadIdx.x, wid = tid >> 5, lane = tid & 31;
    int grp = lane >> 2, tig = lane & 3;
    int warpM = wid & 3, warpN = wid >> 2;
    int rowBase = blockIdx.x * 128;
    int wr = warpM * 32;
    int wn = warpN * 64;

    int ar = tid >> 1, aq = tid & 1;
    int wkk = tid >> 5;
    int wnn = (tid & 31) << 2;

    float acc[2][8][4];
#pragma unroll
    for (int mt = 0; mt < 2; ++mt)
#pragma unroll
        for (int nt = 0; nt < 8; ++nt)
#pragma unroll
            for (int q = 0; q < 4; ++q) acc[mt][nt][q] = 0.0f;

    uint4 va[2];
    float4 rw[4];
    {
        int grow = rowBase + ar; if (grow >= M) grow = M - 1;
        const uint4* ap = (const uint4*)(A1 + (size_t)grow * K_DIM + aq * 16);
        va[0] = ap[0];
        va[1] = ap[1];
#pragma unroll
        for (int i = 0; i < 4; ++i) {
            int kk = wkk + i * 8;
            rw[i] = *(const float4*)&W1[(size_t)kk * K_DIM + wnn];
        }
    }

#pragma unroll 1
    for (int cc = 0; cc < 8; ++cc) {
        __syncthreads();
        {
            int base = ar * XPITCH + aq * 8;
            *(uint4*)&Xs[base] = va[0];
            *(uint4*)&Xs[base + 4] = va[1];
        }
        {
            __nv_bfloat16* WB = (__nv_bfloat16*)Ws;
#pragma unroll
            for (int i = 0; i < 4; ++i) {
                int kk = wkk + i * 8;
                WB[(wnn + 0) * (2 * XPITCH) + kk] = __float2bfloat16(rw[i].x);
                WB[(wnn + 1) * (2 * XPITCH) + kk] = __float2bfloat16(rw[i].y);
                WB[(wnn + 2) * (2 * XPITCH) + kk] = __float2bfloat16(rw[i].z);
                WB[(wnn + 3) * (2 * XPITCH) + kk] = __float2bfloat16(rw[i].w);
            }
        }
        __syncthreads();
        if (cc < 7) {
            int nc = cc + 1;
            const __nv_bfloat16* A = (nc >= 4) ? A2 : A1;
            const float* W = (nc >= 4) ? W2 : W1;
            int k0 = (nc & 3) * 32;
            int grow = rowBase + ar; if (grow >= M) grow = M - 1;
            const uint4* ap = (const uint4*)(A + (size_t)grow * K_DIM + k0 + aq * 16);
            va[0] = ap[0];
            va[1] = ap[1];
#pragma unroll
            for (int i = 0; i < 4; ++i) {
                int kk = wkk + i * 8;
                rw[i] = *(const float4*)&W[(size_t)(k0 + kk) * K_DIM + wnn];
            }
        }
#pragma unroll
        for (int ks = 0; ks < 2; ++ks) {
            int kw = ks * 8;
            uint32_t af[2][4];
#pragma unroll
            for (int mt = 0; mt < 2; ++mt) {
                int r = wr + mt * 16 + grp;
                af[mt][0] = Xs[r * XPITCH + kw + tig];
                af[mt][1] = Xs[(r + 8) * XPITCH + kw + tig];
                af[mt][2] = Xs[r * XPITCH + kw + tig + 4];
                af[mt][3] = Xs[(r + 8) * XPITCH + kw + tig + 4];
            }
#pragma unroll
            for (int nt = 0; nt < 8; ++nt) {
                int n = wn + nt * 8 + grp;
                uint32_t b0 = Ws[n * XPITCH + kw + tig];
                uint32_t b1 = Ws[n * XPITCH + kw + tig + 4];
                mma_bf16(acc[0][nt], af[0][0], af[0][1], af[0][2], af[0][3], b0, b1);
                mma_bf16(acc[1][nt], af[1][0], af[1][1], af[1][2], af[1][3], b0, b1);
            }
        }
    }

    // epilogue: bias + ReLU; bf16 + fp8 shadow stores (no fp32 h1)
#pragma unroll
    for (int mt = 0; mt < 2; ++mt) {
        int r0g = rowBase + wr + mt * 16 + grp;
        int r1g = r0g + 8;
#pragma unroll
        for (int nt = 0; nt < 8; ++nt) {
            int col = wn + nt * 8 + 2 * tig;
            float2 bv = *(const float2*)&bias[col];
            if (r0g < M) {
                float vx = fmaxf(acc[mt][nt][0] + bv.x, 0.0f);
                float vy = fmaxf(acc[mt][nt][1] + bv.y, 0.0f);
                __nv_bfloat162 hb = __floats2bfloat162_rn(vx, vy);
                *(__nv_bfloat162*)&Cb[(size_t)r0g * K_DIM + col] = hb;
                unsigned short p;
                asm("cvt.rn.satfinite.e4m3x2.f32 %0, %1, %2;" : "=h"(p) : "f"(vy), "f"(vx));
                *(unsigned short*)(C8 + (size_t)r0g * K_DIM + col) = p;
            }
            if (r1g < M) {
                float vx = fmaxf(acc[mt][nt][2] + bv.x, 0.0f);
                float vy = fmaxf(acc[mt][nt][3] + bv.y, 0.0f);
                __nv_bfloat162 hb = __floats2bfloat162_rn(vx, vy);
                *(__nv_bfloat162*)&Cb[(size_t)r1g * K_DIM + col] = hb;
                unsigned short p;
                asm("cvt.rn.satfinite.e4m3x2.f32 %0, %1, %2;" : "=h"(p) : "f"(vy), "f"(vx));
                *(unsigned short*)(C8 + (size_t)r1g * K_DIM + col) = p;
            }
        }
    }
}

// ---------------------------------------------------------------------------
// 5) fused SpMM2 + per-graph sums: block = 16 warps = 16 graph-sorted nodes.
//    fp8 neighbor gather; own row read from bf16 shadow; block-level segmented
//    reduction; spread atomics.
__global__ __launch_bounds__(512)
void k_spmm_gs2(const uint8_t* __restrict__ X8,          // fp8 h1
                const __nv_bfloat16* __restrict__ H,      // bf16 h1
                const int* __restrict__ gid) {
    __shared__ float smean[16][K_DIM];
    __shared__ float sh1[16][K_DIM];
    __shared__ int sg[16];
    int wid = threadIdx.x >> 5, lane = threadIdx.x & 31;
    int node = blockIdx.x * 16 + wid;                     // 100000 = 6250*16
    int e0 = g_rowptr[node], e1 = g_rowptr[node + 1];
    int half = lane >> 4, sub = lane & 15;
    float a[8];
    gather_node8(X8, e0, e1, half, sub, a);
    float inv = (e1 > e0) ? 1.0f / (float)(e1 - e0) : 0.0f;
    int jb = half * 4;
    float4 mv;
    mv.x = a[jb + 0] * inv; mv.y = a[jb + 1] * inv;
    mv.z = a[jb + 2] * inv; mv.w = a[jb + 3] * inv;
    *(float4*)&smean[wid][sub * 8 + half * 4] = mv;
    uint2 u = *((const uint2*)(H + (size_t)node * K_DIM) + lane);
    float4 hv;
    hv.x = __uint_as_float(u.x << 16);
    hv.y = __uint_as_float(u.x & 0xFFFF0000u);
    hv.z = __uint_as_float(u.y << 16);
    hv.w = __uint_as_float(u.y & 0xFFFF0000u);
    *(float4*)&sh1[wid][lane * 4] = hv;
    if (lane == 0) sg[wid] = gid[node];
    __syncthreads();

    int t = threadIdx.x;
    if (t < 256) {
        int d = t & 127;
        float* dstArr = (t < 128) ? g_gs1 : g_gs2;
        int cur = sg[0];
        float acc = 0.0f;
#pragma unroll
        for (int w = 0; w < 16; ++w) {
            int g = sg[w];
            float v = (t < 128) ? sh1[w][d] : smean[w][d];
            if (g != cur) {
                atomicAdd(&dstArr[cur * K_DIM + d], acc);
                acc = 0.0f; cur = g;
            }
            acc += v;
        }
        atomicAdd(&dstArr[cur * K_DIM + d], acc);
    } else if (t == 256) {
        int cur = sg[0], c = 0;
#pragma unroll
        for (int w = 0; w < 16; ++w) {
            int g = sg[w];
            if (g != cur) { atomicAdd(&g_gcnt[cur], c); c = 0; cur = g; }
            ++c;
        }
        atomicAdd(&g_gcnt[cur], c);
    }
}

// ---------------------------------------------------------------------------
// 6) fused: hg = (gs1@W2s + gs2@W2n)/cnt + b2 ; out = [hg|perm]@Wc + bc
//    Re-zeroes gs1/gs2/gcnt for the next kernel_launch call.
__global__ void k_hgcls(const float* __restrict__ W2s, const float* __restrict__ W2n,
                        const float* __restrict__ b2,
                        const float* __restrict__ perm,
                        const float* __restrict__ Wc,
                        const float* __restrict__ bc,
                        float* __restrict__ out) {
    __shared__ float s1[K_DIM], s2[K_DIM], hgs[K_DIM];
    __shared__ float red[K_CLS];
    __shared__ int scnt;
    int g = blockIdx.x, d = threadIdx.x;
    s1[d] = g_gs1[g * K_DIM + d];
    s2[d] = g_gs2[g * K_DIM + d];
    if (d == 0) scnt = g_gcnt[g];
    if (d < K_CLS) red[d] = bc[d];
    __syncthreads();
    g_gs1[g * K_DIM + d] = 0.0f;       // zero-invariant for next call
    g_gs2[g * K_DIM + d] = 0.0f;
    if (d == 0) g_gcnt[g] = 0;
    float acc = 0.0f;
#pragma unroll 4
    for (int k = 0; k < K_DIM; ++k)
        acc += s1[k] * W2s[k * K_DIM + d] + s2[k] * W2n[k * K_DIM + d];
    int cnt = scnt;
    float inv = 1.0f / (float)(cnt > 1 ? cnt : 1);
    hgs[d] = acc * inv + b2[d];
    __syncthreads();
    if (d < 64) {
        int c = d & 7, seg = d >> 3;
        int k0 = seg * 32;
        float p = 0.0f;
#pragma unroll 4
        for (int k = k0; k < k0 + 32; ++k) {
            float val = (k < K_DIM) ? hgs[k] : perm[g * K_DIM + (k - K_DIM)];
            p += val * Wc[k * K_CLS + c];
        }
        atomicAdd(&red[c], p);
    }
    __syncthreads();
    if (d < K_CLS) out[g * K_CLS + d] = red[d];
}

// ---------------------------------------------------------------------------
extern "C" void kernel_launch(void* const* d_in, const int* in_sizes, int n_in,
                              void* d_out, int out_size) {
    const float* h    = (const float*)d_in[0];
    const float* perm = (const float*)d_in[1];
    const int*   src  = (const int*)  d_in[2];
    const int*   dst  = (const int*)  d_in[3];
    const int*   gid  = (const int*)  d_in[4];
    const float* W1s  = (const float*)d_in[5];
    const float* W1n  = (const float*)d_in[6];
    const float* b1   = (const float*)d_in[7];
    const float* W2s  = (const float*)d_in[8];
    const float* W2n  = (const float*)d_in[9];
    const float* b2   = (const float*)d_in[10];
    const float* Wc   = (const float*)d_in[11];
    const float* bc   = (const float*)d_in[12];
    float* out = (float*)d_out;
    (void)in_sizes; (void)n_in; (void)out_size;

    __nv_bfloat16* hbb;     cudaGetSymbolAddress((void**)&hbb,   g_hb);
    __nv_bfloat16* mbb;     cudaGetSymbolAddress((void**)&mbb,   g_mb);
    __nv_bfloat16* h1bb;    cudaGetSymbolAddress((void**)&h1bb,  g_h1b);
    uint8_t* h8;            cudaGetSymbolAddress((void**)&h8,    g_h8);
    uint8_t* h18;           cudaGetSymbolAddress((void**)&h18,   g_h18);

    // CSR build (3 launches)
    k_prep<<<(K_QUADS + 255) / 256, 256>>>(h, hbb, h8, dst);
    k_scan<<<K_NB, 256>>>();
    k_fill<<<(K_EDGES + 255) / 256, 256>>>(src, dst);

    int spmmBlocks = (K_NODES * 32 + 255) / 256;
    int gemmBlocks = (K_NODES + 127) / 128;

    // layer 1
    k_spmm1<<<spmmBlocks, 256>>>(h8, mbb);
    k_gemm_bf16<<<gemmBlocks, 256>>>(hbb, mbb, W1s, W1n, b1, h1bb, h18, K_NODES);

    // layer 2 on graph means: fused SpMM2 + per-graph sums, then readout
    k_spmm_gs2<<<K_NODES / 16, 512>>>(h18, h1bb, gid);
    k_hgcls<<<K_GRAPHS, K_DIM>>>(W2s, W2n, b2, perm, Wc, bc, out);
}

// round 13
// speedup vs baseline: 1.3812x; 1.0165x over previous
#include <cuda_runtime.h>
#include <cuda_bf16.h>
#include <cuda_fp16.h>
#include <cstdint>
#include <cstring>

// ---------------------------------------------------------------------------
// GraphSAGE (2-layer, mean agg) + graph-mean readout + linear classifier.
// R13: quarter-warp uint4 fp8 gather (4 edges in flight/warp, LDG.128,
// predicated tails) in both gather kernels.  Rest identical to R12 (252us).
// ---------------------------------------------------------------------------

#define K_NODES  100000
#define K_EDGES  1600000
#define K_GRAPHS 64
#define K_DIM    128
#define K_CLS    8
#define K_NB     98            // ceil(100000/1024)
#define K_QUADS  (K_NODES * K_DIM / 4)

// scratch (static device memory; no allocations)
__device__ int   g_count [K_NODES];            // zero-invariant
__device__ int   g_rowptr[K_NODES + 1];
__device__ int   g_cursor[K_NODES];
__device__ int   g_esrc  [K_EDGES];
__device__ unsigned long long g_state[K_NB];   // packed (flag<<32)|value
__device__ float g_gs1   [K_GRAPHS * K_DIM];   // zero-invariant
__device__ float g_gs2   [K_GRAPHS * K_DIM];   // zero-invariant
__device__ int   g_gcnt  [K_GRAPHS];           // zero-invariant
__device__ __nv_bfloat16 g_hb  [(size_t)K_NODES * K_DIM];   // bf16 h
__device__ __nv_bfloat16 g_mb  [(size_t)K_NODES * K_DIM];   // bf16 mean
__device__ __nv_bfloat16 g_h1b [(size_t)K_NODES * K_DIM];   // bf16 h1
__device__ uint8_t       g_h8  [(size_t)K_NODES * K_DIM];   // fp8 h
__device__ uint8_t       g_h18 [(size_t)K_NODES * K_DIM];   // fp8 h1

// ---------------------------------------------------------------------------
// 0) prep: bf16 + fp8 shadows of h + dst histogram + state reset
__global__ void k_prep(const float* __restrict__ X, __nv_bfloat16* __restrict__ Y,
                       uint8_t* __restrict__ Y8, const int* __restrict__ dst) {
    int i = blockIdx.x * blockDim.x + threadIdx.x;
    if (i < K_NB) g_state[i] = 0ull;
    if (i < K_QUADS) {
        float4 v = *((const float4*)X + i);
        __nv_bfloat162 a = __floats2bfloat162_rn(v.x, v.y);
        __nv_bfloat162 b = __floats2bfloat162_rn(v.z, v.w);
        uint2 u;
        memcpy(&u.x, &a, 4);
        memcpy(&u.y, &b, 4);
        *((uint2*)Y + i) = u;
        unsigned short p01, p23;
        asm("cvt.rn.satfinite.e4m3x2.f32 %0, %1, %2;" : "=h"(p01) : "f"(v.y), "f"(v.x));
        asm("cvt.rn.satfinite.e4m3x2.f32 %0, %1, %2;" : "=h"(p23) : "f"(v.w), "f"(v.z));
        ((uint32_t*)Y8)[i] = (uint32_t)p01 | ((uint32_t)p23 << 16);
    }
    if (i < K_EDGES) atomicAdd(&g_count[dst[i]], 1);
}

// 1) single-pass scan (decoupled lookback, packed flag|value) -> rowptr,cursor
__global__ void k_scan() {
    __shared__ int sm[256];
    __shared__ int sExcl;
    int b = blockIdx.x, t = threadIdx.x;
    int base = b * 1024 + t * 4;
    int c[4];
    int s = 0;
#pragma unroll
    for (int j = 0; j < 4; ++j) {
        int i = base + j;
        c[j] = (i < K_NODES) ? g_count[i] : 0;
        if (i < K_NODES) g_count[i] = 0;       // maintain zero-invariant
        s += c[j];
    }
    sm[t] = s;
    __syncthreads();
    for (int o = 1; o < 256; o <<= 1) {
        int u = (t >= o) ? sm[t - o] : 0;
        __syncthreads();
        sm[t] += u;
        __syncthreads();
    }
    int S = sm[255];
    if (t == 0) {
        if (b == 0) {
            atomicExch(&g_state[0], (2ull << 32) | (unsigned int)S);
            sExcl = 0;
        } else {
            atomicExch(&g_state[b], (1ull << 32) | (unsigned int)S);
            int excl = 0, p = b - 1;
            while (true) {
                unsigned long long v = atomicAdd(&g_state[p], 0ull);
                unsigned int f = (unsigned int)(v >> 32);
                if (f == 0) continue;
                excl += (int)(unsigned int)v;
                if (f == 2) break;
                --p;
            }
            atomicExch(&g_state[b], (2ull << 32) | (unsigned int)(excl + S));
            sExcl = excl;
        }
    }
    __syncthreads();
    int off = sExcl + sm[t] - s;
#pragma unroll
    for (int j = 0; j < 4; ++j) {
        int i = base + j;
        if (i < K_NODES) {
            g_rowptr[i] = off;
            g_cursor[i] = off;
        }
        off += c[j];
    }
    if (b == K_NB - 1 && t == 255) g_rowptr[K_NODES] = sExcl + S;
}

// 2) bucket fill: sort edge srcs by dst
__global__ void k_fill(const int* __restrict__ src, const int* __restrict__ dst) {
    int i = blockIdx.x * blockDim.x + threadIdx.x;
    if (i < K_EDGES) {
        int p = atomicAdd(&g_cursor[dst[i]], 1);
        g_esrc[p] = src[i];
    }
}

// ---------------------------------------------------------------------------
// fp8 quarter-warp gather: 4 edges in flight per warp; each lane loads uint4
// (16 fp8 dims) of its quarter's edge; decode e4m3x2->f16x2, HADD2 accumulate;
// two HADD2-shfl steps reduce across quarters.  Returns lane's float4 slice
// for dims sub8*16 + quarter*4 .. +3 (UNSCALED sum).
__device__ __forceinline__ void dec16(uint4 u, __half2* acc) {
    uint32_t w[4] = {u.x, u.y, u.z, u.w};
#pragma unroll
    for (int i = 0; i < 4; ++i) {
        uint32_t r0, r1;
        asm("cvt.rn.f16x2.e4m3x2 %0, %1;" : "=r"(r0) : "h"((unsigned short)(w[i] & 0xFFFFu)));
        asm("cvt.rn.f16x2.e4m3x2 %0, %1;" : "=r"(r1) : "h"((unsigned short)(w[i] >> 16)));
        __half2 h0, h1;
        memcpy(&h0, &r0, 4);
        memcpy(&h1, &r1, 4);
        acc[2 * i]     = __hadd2(acc[2 * i], h0);
        acc[2 * i + 1] = __hadd2(acc[2 * i + 1], h1);
    }
}
__device__ __forceinline__ __half2 h2shfl_xor(__half2 v, int m) {
    uint32_t u;
    memcpy(&u, &v, 4);
    u = __shfl_xor_sync(0xffffffffu, u, m);
    __half2 r;
    memcpy(&r, &u, 4);
    return r;
}

__device__ __forceinline__ float4 gather_node4(const uint8_t* __restrict__ X8,
                                               int e0, int e1, int quarter, int sub8) {
    const char* base = (const char*)X8 + sub8 * 16;
    __half2 acc[8];
    __half2 hz = __float2half2_rn(0.0f);
#pragma unroll
    for (int j = 0; j < 8; ++j) acc[j] = hz;

    int e = e0;
    for (; e + 8 <= e1; e += 8) {                 // 2 predication-free rounds
        int s0 = g_esrc[e + quarter];
        int s1 = g_esrc[e + 4 + quarter];
        uint4 u0 = *(const uint4*)(base + (size_t)s0 * 128);
        uint4 u1 = *(const uint4*)(base + (size_t)s1 * 128);
        dec16(u0, acc);
        dec16(u1, acc);
    }
    for (; e < e1; e += 4) {                      // predicated tail (quarter-uniform)
        int idx = e + quarter;
        if (idx < e1) {
            int s = g_esrc[idx];
            uint4 u = *(const uint4*)(base + (size_t)s * 128);
            dec16(u, acc);
        }
    }
    // reduce across quarters (lane bits 3 and 4)
#pragma unroll
    for (int j = 0; j < 8; ++j) {
        acc[j] = __hadd2(acc[j], h2shfl_xor(acc[j], 8));
        acc[j] = __hadd2(acc[j], h2shfl_xor(acc[j], 16));
    }
    float2 f0 = __half22float2(acc[2 * quarter]);
    float2 f1 = __half22float2(acc[2 * quarter + 1]);
    float4 r;
    r.x = f0.x; r.y = f0.y; r.z = f1.x; r.w = f1.y;
    return r;
}

// 3) SpMM mean (layer 1): warp per node, fp8 gather -> bf16 mean row
__global__ void k_spmm1(const uint8_t* __restrict__ X8,
                        __nv_bfloat16* __restrict__ Y) {
    int w = (blockIdx.x * blockDim.x + threadIdx.x) >> 5;
    int lane = threadIdx.x & 31;
    if (w >= K_NODES) return;
    int e0 = g_rowptr[w], e1 = g_rowptr[w + 1];
    int quarter = lane >> 3, sub8 = lane & 7;
    float4 a = gather_node4(X8, e0, e1, quarter, sub8);
    float inv = (e1 > e0) ? 1.0f / (float)(e1 - e0) : 0.0f;
    __nv_bfloat162 p0 = __floats2bfloat162_rn(a.x * inv, a.y * inv);
    __nv_bfloat162 p1 = __floats2bfloat162_rn(a.z * inv, a.w * inv);
    uint2 st;
    memcpy(&st.x, &p0, 4);
    memcpy(&st.y, &p1, 4);
    *((uint2*)(Y + (size_t)w * K_DIM + sub8 * 16 + quarter * 4)) = st;
}

// ---------------------------------------------------------------------------
// 4) bf16 m16n8k16 dual GEMM: h1 = relu(A1@W1 + A2@W2 + bias)
__device__ __forceinline__ void mma_bf16(float* c, uint32_t a0, uint32_t a1,
                                         uint32_t a2, uint32_t a3,
                                         uint32_t b0, uint32_t b1) {
    asm volatile(
        "mma.sync.aligned.m16n8k16.row.col.f32.bf16.bf16.f32 "
        "{%0,%1,%2,%3}, {%4,%5,%6,%7}, {%8,%9}, {%0,%1,%2,%3};"
        : "+f"(c[0]), "+f"(c[1]), "+f"(c[2]), "+f"(c[3])
        : "r"(a0), "r"(a1), "r"(a2), "r"(a3), "r"(b0), "r"(b1));
}

#define XPITCH 20   // words per 32-k row (16 data + 4 pad); mult of 4

__global__ __launch_bounds__(256, 2)
void k_gemm_bf16(const __nv_bfloat16* __restrict__ A1,
                 const __nv_bfloat16* __restrict__ A2,
                 const float* __restrict__ W1, const float* __restrict__ W2,
                 const float* __restrict__ bias,
                 __nv_bfloat16* __restrict__ Cb, uint8_t* __restrict__ C8, int M) {
    __shared__ __align__(16) uint32_t Xs[128 * XPITCH];
    __shared__ __align__(16) uint32_t Ws[128 * XPITCH];
    int tid = threadIdx.x, wid = tid >> 5, lane = tid & 31;
    int grp = lane >> 2, tig = lane & 3;
    int warpM = wid & 3, warpN = wid >> 2;
    int rowBase = blockIdx.x * 128;
    int wr = warpM * 32;
    int wn = warpN * 64;

    int ar = tid >> 1, aq = tid & 1;
    int wkk = tid >> 5;
    int wnn = (tid & 31) << 2;

    float acc[2][8][4];
#pragma unroll
    for (int mt = 0; mt < 2; ++mt)
#pragma unroll
        for (int nt = 0; nt < 8; ++nt)
#pragma unroll
            for (int q = 0; q < 4; ++q) acc[mt][nt][q] = 0.0f;

    uint4 va[2];
    float4 rw[4];
    {
        int grow = rowBase + ar; if (grow >= M) grow = M - 1;
        const uint4* ap = (const uint4*)(A1 + (size_t)grow * K_DIM + aq * 16);
        va[0] = ap[0];
        va[1] = ap[1];
#pragma unroll
        for (int i = 0; i < 4; ++i) {
            int kk = wkk + i * 8;
            rw[i] = *(const float4*)&W1[(size_t)kk * K_DIM + wnn];
        }
    }

#pragma unroll 1
    for (int cc = 0; cc < 8; ++cc) {
        __syncthreads();
        {
            int base = ar * XPITCH + aq * 8;
            *(uint4*)&Xs[base] = va[0];
            *(uint4*)&Xs[base + 4] = va[1];
        }
        {
            __nv_bfloat16* WB = (__nv_bfloat16*)Ws;
#pragma unroll
            for (int i = 0; i < 4; ++i) {
                int kk = wkk + i * 8;
                WB[(wnn + 0) * (2 * XPITCH) + kk] = __float2bfloat16(rw[i].x);
                WB[(wnn + 1) * (2 * XPITCH) + kk] = __float2bfloat16(rw[i].y);
                WB[(wnn + 2) * (2 * XPITCH) + kk] = __float2bfloat16(rw[i].z);
                WB[(wnn + 3) * (2 * XPITCH) + kk] = __float2bfloat16(rw[i].w);
            }
        }
        __syncthreads();
        if (cc < 7) {
            int nc = cc + 1;
            const __nv_bfloat16* A = (nc >= 4) ? A2 : A1;
            const float* W = (nc >= 4) ? W2 : W1;
            int k0 = (nc & 3) * 32;
            int grow = rowBase + ar; if (grow >= M) grow = M - 1;
            const uint4* ap = (const uint4*)(A + (size_t)grow * K_DIM + k0 + aq * 16);
            va[0] = ap[0];
            va[1] = ap[1];
#pragma unroll
            for (int i = 0; i < 4; ++i) {
                int kk = wkk + i * 8;
                rw[i] = *(const float4*)&W[(size_t)(k0 + kk) * K_DIM + wnn];
            }
        }
#pragma unroll
        for (int ks = 0; ks < 2; ++ks) {
            int kw = ks * 8;
            uint32_t af[2][4];
#pragma unroll
            for (int mt = 0; mt < 2; ++mt) {
                int r = wr + mt * 16 + grp;
                af[mt][0] = Xs[r * XPITCH + kw + tig];
                af[mt][1] = Xs[(r + 8) * XPITCH + kw + tig];
                af[mt][2] = Xs[r * XPITCH + kw + tig + 4];
                af[mt][3] = Xs[(r + 8) * XPITCH + kw + tig + 4];
            }
#pragma unroll
            for (int nt = 0; nt < 8; ++nt) {
                int n = wn + nt * 8 + grp;
                uint32_t b0 = Ws[n * XPITCH + kw + tig];
                uint32_t b1 = Ws[n * XPITCH + kw + tig + 4];
                mma_bf16(acc[0][nt], af[0][0], af[0][1], af[0][2], af[0][3], b0, b1);
                mma_bf16(acc[1][nt], af[1][0], af[1][1], af[1][2], af[1][3], b0, b1);
            }
        }
    }

    // epilogue: bias + ReLU; bf16 + fp8 shadow stores
#pragma unroll
    for (int mt = 0; mt < 2; ++mt) {
        int r0g = rowBase + wr + mt * 16 + grp;
        int r1g = r0g + 8;
#pragma unroll
        for (int nt = 0; nt < 8; ++nt) {
            int col = wn + nt * 8 + 2 * tig;
            float2 bv = *(const float2*)&bias[col];
            if (r0g < M) {
                float vx = fmaxf(acc[mt][nt][0] + bv.x, 0.0f);
                float vy = fmaxf(acc[mt][nt][1] + bv.y, 0.0f);
                __nv_bfloat162 hb = __floats2bfloat162_rn(vx, vy);
                *(__nv_bfloat162*)&Cb[(size_t)r0g * K_DIM + col] = hb;
                unsigned short p;
                asm("cvt.rn.satfinite.e4m3x2.f32 %0, %1, %2;" : "=h"(p) : "f"(vy), "f"(vx));
                *(unsigned short*)(C8 + (size_t)r0g * K_DIM + col) = p;
            }
            if (r1g < M) {
                float vx = fmaxf(acc[mt][nt][2] + bv.x, 0.0f);
                float vy = fmaxf(acc[mt][nt][3] + bv.y, 0.0f);
                __nv_bfloat162 hb = __floats2bfloat162_rn(vx, vy);
                *(__nv_bfloat162*)&Cb[(size_t)r1g * K_DIM + col] = hb;
                unsigned short p;
                asm("cvt.rn.satfinite.e4m3x2.f32 %0, %1, %2;" : "=h"(p) : "f"(vy), "f"(vx));
                *(unsigned short*)(C8 + (size_t)r1g * K_DIM + col) = p;
            }
        }
    }
}

// ---------------------------------------------------------------------------
// 5) fused SpMM2 + per-graph sums: block = 16 warps = 16 graph-sorted nodes.
__global__ __launch_bounds__(512)
void k_spmm_gs2(const uint8_t* __restrict__ X8,          // fp8 h1
                const __nv_bfloat16* __restrict__ H,      // bf16 h1
                const int* __restrict__ gid) {
    __shared__ float smean[16][K_DIM];
    __shared__ float sh1[16][K_DIM];
    __shared__ int sg[16];
    int wid = threadIdx.x >> 5, lane = threadIdx.x & 31;
    int node = blockIdx.x * 16 + wid;                     // 100000 = 6250*16
    int e0 = g_rowptr[node], e1 = g_rowptr[node + 1];
    int quarter = lane >> 3, sub8 = lane & 7;
    float4 a = gather_node4(X8, e0, e1, quarter, sub8);
    float inv = (e1 > e0) ? 1.0f / (float)(e1 - e0) : 0.0f;
    float4 mv;
    mv.x = a.x * inv; mv.y = a.y * inv; mv.z = a.z * inv; mv.w = a.w * inv;
    *(float4*)&smean[wid][sub8 * 16 + quarter * 4] = mv;
    uint2 u = *((const uint2*)(H + (size_t)node * K_DIM) + lane);
    float4 hv;
    hv.x = __uint_as_float(u.x << 16);
    hv.y = __uint_as_float(u.x & 0xFFFF0000u);
    hv.z = __uint_as_float(u.y << 16);
    hv.w = __uint_as_float(u.y & 0xFFFF0000u);
    *(float4*)&sh1[wid][lane * 4] = hv;
    if (lane == 0) sg[wid] = gid[node];
    __syncthreads();

    int t = threadIdx.x;
    if (t < 256) {
        int d = t & 127;
        float* dstArr = (t < 128) ? g_gs1 : g_gs2;
        int cur = sg[0];
        float acc = 0.0f;
#pragma unroll
        for (int w = 0; w < 16; ++w) {
            int g = sg[w];
            float v = (t < 128) ? sh1[w][d] : smean[w][d];
            if (g != cur) {
                atomicAdd(&dstArr[cur * K_DIM + d], acc);
                acc = 0.0f; cur = g;
            }
            acc += v;
        }
        atomicAdd(&dstArr[cur * K_DIM + d], acc);
    } else if (t == 256) {
        int cur = sg[0], c = 0;
#pragma unroll
        for (int w = 0; w < 16; ++w) {
            int g = sg[w];
            if (g != cur) { atomicAdd(&g_gcnt[cur], c); c = 0; cur = g; }
            ++c;
        }
        atomicAdd(&g_gcnt[cur], c);
    }
}

// ---------------------------------------------------------------------------
// 6) fused: hg = (gs1@W2s + gs2@W2n)/cnt + b2 ; out = [hg|perm]@Wc + bc
//    Re-zeroes gs1/gs2/gcnt for the next kernel_launch call.
__global__ void k_hgcls(const float* __restrict__ W2s, const float* __restrict__ W2n,
                        const float* __restrict__ b2,
                        const float* __restrict__ perm,
                        const float* __restrict__ Wc,
                        const float* __restrict__ bc,
                        float* __restrict__ out) {
    __shared__ float s1[K_DIM], s2[K_DIM], hgs[K_DIM];
    __shared__ float red[K_CLS];
    __shared__ int scnt;
    int g = blockIdx.x, d = threadIdx.x;
    s1[d] = g_gs1[g * K_DIM + d];
    s2[d] = g_gs2[g * K_DIM + d];
    if (d == 0) scnt = g_gcnt[g];
    if (d < K_CLS) red[d] = bc[d];
    __syncthreads();
    g_gs1[g * K_DIM + d] = 0.0f;       // zero-invariant for next call
    g_gs2[g * K_DIM + d] = 0.0f;
    if (d == 0) g_gcnt[g] = 0;
    float acc = 0.0f;
#pragma unroll 4
    for (int k = 0; k < K_DIM; ++k)
        acc += s1[k] * W2s[k * K_DIM + d] + s2[k] * W2n[k * K_DIM + d];
    int cnt = scnt;
    float inv = 1.0f / (float)(cnt > 1 ? cnt : 1);
    hgs[d] = acc * inv + b2[d];
    __syncthreads();
    if (d < 64) {
        int c = d & 7, seg = d >> 3;
        int k0 = seg * 32;
        float p = 0.0f;
#pragma unroll 4
        for (int k = k0; k < k0 + 32; ++k) {
            float val = (k < K_DIM) ? hgs[k] : perm[g * K_DIM + (k - K_DIM)];
            p += val * Wc[k * K_CLS + c];
        }
        atomicAdd(&red[c], p);
    }
    __syncthreads();
    if (d < K_CLS) out[g * K_CLS + d] = red[d];
}

// ---------------------------------------------------------------------------
extern "C" void kernel_launch(void* const* d_in, const int* in_sizes, int n_in,
                              void* d_out, int out_size) {
    const float* h    = (const float*)d_in[0];
    const float* perm = (const float*)d_in[1];
    const int*   src  = (const int*)  d_in[2];
    const int*   dst  = (const int*)  d_in[3];
    const int*   gid  = (const int*)  d_in[4];
    const float* W1s  = (const float*)d_in[5];
    const float* W1n  = (const float*)d_in[6];
    const float* b1   = (const float*)d_in[7];
    const float* W2s  = (const float*)d_in[8];
    const float* W2n  = (const float*)d_in[9];
    const float* b2   = (const float*)d_in[10];
    const float* Wc   = (const float*)d_in[11];
    const float* bc   = (const float*)d_in[12];
    float* out = (float*)d_out;
    (void)in_sizes; (void)n_in; (void)out_size;

    __nv_bfloat16* hbb;     cudaGetSymbolAddress((void**)&hbb,   g_hb);
    __nv_bfloat16* mbb;     cudaGetSymbolAddress((void**)&mbb,   g_mb);
    __nv_bfloat16* h1bb;    cudaGetSymbolAddress((void**)&h1bb,  g_h1b);
    uint8_t* h8;            cudaGetSymbolAddress((void**)&h8,    g_h8);
    uint8_t* h18;           cudaGetSymbolAddress((void**)&h18,   g_h18);

    // CSR build (3 launches)
    k_prep<<<(K_QUADS + 255) / 256, 256>>>(h, hbb, h8, dst);
    k_scan<<<K_NB, 256>>>();
    k_fill<<<(K_EDGES + 255) / 256, 256>>>(src, dst);

    int spmmBlocks = (K_NODES * 32 + 255) / 256;
    int gemmBlocks = (K_NODES + 127) / 128;

    // layer 1
    k_spmm1<<<spmmBlocks, 256>>>(h8, mbb);
    k_gemm_bf16<<<gemmBlocks, 256>>>(hbb, mbb, W1s, W1n, b1, h1bb, h18, K_NODES);

    // layer 2 on graph means: fused SpMM2 + per-graph sums, then readout
    k_spmm_gs2<<<K_NODES / 16, 512>>>(h18, h1bb, gid);
    k_hgcls<<<K_GRAPHS, K_DIM>>>(W2s, W2n, b2, perm, Wc, bc, out);
}

// round 14
// speedup vs baseline: 1.6920x; 1.2250x over previous
#include <cuda_runtime.h>
#include <cuda_bf16.h>
#include <cuda_fp16.h>
#include <cstdint>
#include <cstring>

// ---------------------------------------------------------------------------
// GraphSAGE (2-layer, mean agg) + graph-mean readout + linear classifier.
// R14: esrc stores byte offsets (no per-load IMAD); W pre-converted to a
// combined bf16 [n][256k] buffer in prep; GEMM stages W raw (uint4, no cvt,
// half the W bytes).  Numerics identical to R13 (247.9us).
// ---------------------------------------------------------------------------

#define K_NODES  100000
#define K_EDGES  1600000
#define K_GRAPHS 64
#define K_DIM    128
#define K_CLS    8
#define K_NB     98            // ceil(100000/1024)
#define K_QUADS  (K_NODES * K_DIM / 4)

// scratch (static device memory; no allocations)
__device__ int   g_count [K_NODES];            // zero-invariant
__device__ int   g_rowptr[K_NODES + 1];
__device__ int   g_cursor[K_NODES];
__device__ int   g_esrc  [K_EDGES];            // BYTE offsets (src*128)
__device__ unsigned long long g_state[K_NB];   // packed (flag<<32)|value
__device__ float g_gs1   [K_GRAPHS * K_DIM];   // zero-invariant
__device__ float g_gs2   [K_GRAPHS * K_DIM];   // zero-invariant
__device__ int   g_gcnt  [K_GRAPHS];           // zero-invariant
__device__ __nv_bfloat16 g_hb  [(size_t)K_NODES * K_DIM];   // bf16 h
__device__ __nv_bfloat16 g_mb  [(size_t)K_NODES * K_DIM];   // bf16 mean
__device__ __nv_bfloat16 g_h1b [(size_t)K_NODES * K_DIM];   // bf16 h1
__device__ uint8_t       g_h8  [(size_t)K_NODES * K_DIM];   // fp8 h
__device__ uint8_t       g_h18 [(size_t)K_NODES * K_DIM];   // fp8 h1
__device__ __nv_bfloat16 g_wb  [128 * 256];                 // bf16 W [n][k], k<128=W1s,>=128=W1n

// ---------------------------------------------------------------------------
// 0) prep: bf16 + fp8 shadows of h + W bf16 transpose + histogram + state reset
__global__ void k_prep(const float* __restrict__ X, __nv_bfloat16* __restrict__ Y,
                       uint8_t* __restrict__ Y8, const int* __restrict__ dst,
                       const float* __restrict__ W1s, const float* __restrict__ W1n) {
    int i = blockIdx.x * blockDim.x + threadIdx.x;
    if (i < K_NB) g_state[i] = 0ull;
    if (i < 128 * 256) {                       // W transpose + bf16 cvt (once)
        int n = i >> 8, k = i & 255;
        float v = (k < 128) ? W1s[k * 128 + n] : W1n[(k - 128) * 128 + n];
        g_wb[i] = __float2bfloat16(v);
    }
    if (i < K_QUADS) {
        float4 v = *((const float4*)X + i);
        __nv_bfloat162 a = __floats2bfloat162_rn(v.x, v.y);
        __nv_bfloat162 b = __floats2bfloat162_rn(v.z, v.w);
        uint2 u;
        memcpy(&u.x, &a, 4);
        memcpy(&u.y, &b, 4);
        *((uint2*)Y + i) = u;
        unsigned short p01, p23;
        asm("cvt.rn.satfinite.e4m3x2.f32 %0, %1, %2;" : "=h"(p01) : "f"(v.y), "f"(v.x));
        asm("cvt.rn.satfinite.e4m3x2.f32 %0, %1, %2;" : "=h"(p23) : "f"(v.w), "f"(v.z));
        ((uint32_t*)Y8)[i] = (uint32_t)p01 | ((uint32_t)p23 << 16);
    }
    if (i < K_EDGES) atomicAdd(&g_count[dst[i]], 1);
}

// 1) single-pass scan (decoupled lookback, packed flag|value) -> rowptr,cursor
__global__ void k_scan() {
    __shared__ int sm[256];
    __shared__ int sExcl;
    int b = blockIdx.x, t = threadIdx.x;
    int base = b * 1024 + t * 4;
    int c[4];
    int s = 0;
#pragma unroll
    for (int j = 0; j < 4; ++j) {
        int i = base + j;
        c[j] = (i < K_NODES) ? g_count[i] : 0;
        if (i < K_NODES) g_count[i] = 0;       // maintain zero-invariant
        s += c[j];
    }
    sm[t] = s;
    __syncthreads();
    for (int o = 1; o < 256; o <<= 1) {
        int u = (t >= o) ? sm[t - o] : 0;
        __syncthreads();
        sm[t] += u;
        __syncthreads();
    }
    int S = sm[255];
    if (t == 0) {
        if (b == 0) {
            atomicExch(&g_state[0], (2ull << 32) | (unsigned int)S);
            sExcl = 0;
        } else {
            atomicExch(&g_state[b], (1ull << 32) | (unsigned int)S);
            int excl = 0, p = b - 1;
            while (true) {
                unsigned long long v = atomicAdd(&g_state[p], 0ull);
                unsigned int f = (unsigned int)(v >> 32);
                if (f == 0) continue;
                excl += (int)(unsigned int)v;
                if (f == 2) break;
                --p;
            }
            atomicExch(&g_state[b], (2ull << 32) | (unsigned int)(excl + S));
            sExcl = excl;
        }
    }
    __syncthreads();
    int off = sExcl + sm[t] - s;
#pragma unroll
    for (int j = 0; j < 4; ++j) {
        int i = base + j;
        if (i < K_NODES) {
            g_rowptr[i] = off;
            g_cursor[i] = off;
        }
        off += c[j];
    }
    if (b == K_NB - 1 && t == 255) g_rowptr[K_NODES] = sExcl + S;
}

// 2) bucket fill: sort edges by dst; store BYTE offsets (src*128)
__global__ void k_fill(const int* __restrict__ src, const int* __restrict__ dst) {
    int i = blockIdx.x * blockDim.x + threadIdx.x;
    if (i < K_EDGES) {
        int p = atomicAdd(&g_cursor[dst[i]], 1);
        g_esrc[p] = src[i] << 7;               // 128 B per fp8 row
    }
}

// ---------------------------------------------------------------------------
// fp8 quarter-warp gather (esrc holds byte offsets)
__device__ __forceinline__ void dec16(uint4 u, __half2* acc) {
    uint32_t w[4] = {u.x, u.y, u.z, u.w};
#pragma unroll
    for (int i = 0; i < 4; ++i) {
        uint32_t r0, r1;
        asm("cvt.rn.f16x2.e4m3x2 %0, %1;" : "=r"(r0) : "h"((unsigned short)(w[i] & 0xFFFFu)));
        asm("cvt.rn.f16x2.e4m3x2 %0, %1;" : "=r"(r1) : "h"((unsigned short)(w[i] >> 16)));
        __half2 h0, h1;
        memcpy(&h0, &r0, 4);
        memcpy(&h1, &r1, 4);
        acc[2 * i]     = __hadd2(acc[2 * i], h0);
        acc[2 * i + 1] = __hadd2(acc[2 * i + 1], h1);
    }
}
__device__ __forceinline__ __half2 h2shfl_xor(__half2 v, int m) {
    uint32_t u;
    memcpy(&u, &v, 4);
    u = __shfl_xor_sync(0xffffffffu, u, m);
    __half2 r;
    memcpy(&r, &u, 4);
    return r;
}

__device__ __forceinline__ float4 gather_node4(const uint8_t* __restrict__ X8,
                                               int e0, int e1, int quarter, int sub8) {
    const char* base = (const char*)X8 + sub8 * 16;
    __half2 acc[8];
    __half2 hz = __float2half2_rn(0.0f);
#pragma unroll
    for (int j = 0; j < 8; ++j) acc[j] = hz;

    int e = e0;
    for (; e + 8 <= e1; e += 8) {
        int s0 = g_esrc[e + quarter];
        int s1 = g_esrc[e + 4 + quarter];
        uint4 u0 = *(const uint4*)(base + (uint32_t)s0);
        uint4 u1 = *(const uint4*)(base + (uint32_t)s1);
        dec16(u0, acc);
        dec16(u1, acc);
    }
    for (; e < e1; e += 4) {
        int idx = e + quarter;
        if (idx < e1) {
            int s = g_esrc[idx];
            uint4 u = *(const uint4*)(base + (uint32_t)s);
            dec16(u, acc);
        }
    }
#pragma unroll
    for (int j = 0; j < 8; ++j) {
        acc[j] = __hadd2(acc[j], h2shfl_xor(acc[j], 8));
        acc[j] = __hadd2(acc[j], h2shfl_xor(acc[j], 16));
    }
    float2 f0 = __half22float2(acc[2 * quarter]);
    float2 f1 = __half22float2(acc[2 * quarter + 1]);
    float4 r;
    r.x = f0.x; r.y = f0.y; r.z = f1.x; r.w = f1.y;
    return r;
}

// 3) SpMM mean (layer 1): warp per node, fp8 gather -> bf16 mean row
__global__ void k_spmm1(const uint8_t* __restrict__ X8,
                        __nv_bfloat16* __restrict__ Y) {
    int w = (blockIdx.x * blockDim.x + threadIdx.x) >> 5;
    int lane = threadIdx.x & 31;
    if (w >= K_NODES) return;
    int e0 = g_rowptr[w], e1 = g_rowptr[w + 1];
    int quarter = lane >> 3, sub8 = lane & 7;
    float4 a = gather_node4(X8, e0, e1, quarter, sub8);
    float inv = (e1 > e0) ? 1.0f / (float)(e1 - e0) : 0.0f;
    __nv_bfloat162 p0 = __floats2bfloat162_rn(a.x * inv, a.y * inv);
    __nv_bfloat162 p1 = __floats2bfloat162_rn(a.z * inv, a.w * inv);
    uint2 st;
    memcpy(&st.x, &p0, 4);
    memcpy(&st.y, &p1, 4);
    *((uint2*)(Y + (size_t)w * K_DIM + sub8 * 16 + quarter * 4)) = st;
}

// ---------------------------------------------------------------------------
// 4) bf16 m16n8k16 dual GEMM: h1 = relu(A1@W1 + A2@W2 + bias)
//    W read raw from pre-converted bf16 [n][256k] buffer.
__device__ __forceinline__ void mma_bf16(float* c, uint32_t a0, uint32_t a1,
                                         uint32_t a2, uint32_t a3,
                                         uint32_t b0, uint32_t b1) {
    asm volatile(
        "mma.sync.aligned.m16n8k16.row.col.f32.bf16.bf16.f32 "
        "{%0,%1,%2,%3}, {%4,%5,%6,%7}, {%8,%9}, {%0,%1,%2,%3};"
        : "+f"(c[0]), "+f"(c[1]), "+f"(c[2]), "+f"(c[3])
        : "r"(a0), "r"(a1), "r"(a2), "r"(a3), "r"(b0), "r"(b1));
}

#define XPITCH 20   // words per 32-k row (16 data + 4 pad); mult of 4

__global__ __launch_bounds__(256, 2)
void k_gemm_bf16(const __nv_bfloat16* __restrict__ A1,
                 const __nv_bfloat16* __restrict__ A2,
                 const __nv_bfloat16* __restrict__ WB,   // [128n][256k] bf16
                 const float* __restrict__ bias,
                 __nv_bfloat16* __restrict__ Cb, uint8_t* __restrict__ C8, int M) {
    __shared__ __align__(16) uint32_t Xs[128 * XPITCH];
    __shared__ __align__(16) uint32_t Ws[128 * XPITCH];
    int tid = threadIdx.x, wid = tid >> 5, lane = tid & 31;
    int grp = lane >> 2, tig = lane & 3;
    int warpM = wid & 3, warpN = wid >> 2;
    int rowBase = blockIdx.x * 128;
    int wr = warpM * 32;
    int wn = warpN * 64;

    int ar = tid >> 1, aq = tid & 1;               // A staging
    int n0 = tid >> 1, j0 = (tid & 1) << 1;        // W staging: 2 uint4/thread

    float acc[2][8][4];
#pragma unroll
    for (int mt = 0; mt < 2; ++mt)
#pragma unroll
        for (int nt = 0; nt < 8; ++nt)
#pragma unroll
            for (int q = 0; q < 4; ++q) acc[mt][nt][q] = 0.0f;

    uint4 va[2], wv[2];
    {
        int grow = rowBase + ar; if (grow >= M) grow = M - 1;
        const uint4* ap = (const uint4*)(A1 + (size_t)grow * K_DIM + aq * 16);
        va[0] = ap[0];
        va[1] = ap[1];
        const uint4* wp = (const uint4*)(WB + n0 * 256 + j0 * 8);
        wv[0] = wp[0];
        wv[1] = wp[1];
    }

#pragma unroll 1
    for (int cc = 0; cc < 8; ++cc) {
        __syncthreads();
        {
            int base = ar * XPITCH + aq * 8;
            *(uint4*)&Xs[base] = va[0];
            *(uint4*)&Xs[base + 4] = va[1];
        }
        {
            int base = n0 * XPITCH + j0 * 4;
            *(uint4*)&Ws[base] = wv[0];
            *(uint4*)&Ws[base + 4] = wv[1];
        }
        __syncthreads();
        if (cc < 7) {
            int nc = cc + 1;
            const __nv_bfloat16* A = (nc >= 4) ? A2 : A1;
            int k0 = (nc & 3) * 32;
            int grow = rowBase + ar; if (grow >= M) grow = M - 1;
            const uint4* ap = (const uint4*)(A + (size_t)grow * K_DIM + k0 + aq * 16);
            va[0] = ap[0];
            va[1] = ap[1];
            const uint4* wp = (const uint4*)(WB + n0 * 256 + nc * 32 + j0 * 8);
            wv[0] = wp[0];
            wv[1] = wp[1];
        }
#pragma unroll
        for (int ks = 0; ks < 2; ++ks) {
            int kw = ks * 8;
            uint32_t af[2][4];
#pragma unroll
            for (int mt = 0; mt < 2; ++mt) {
                int r = wr + mt * 16 + grp;
                af[mt][0] = Xs[r * XPITCH + kw + tig];
                af[mt][1] = Xs[(r + 8) * XPITCH + kw + tig];
                af[mt][2] = Xs[r * XPITCH + kw + tig + 4];
                af[mt][3] = Xs[(r + 8) * XPITCH + kw + tig + 4];
            }
#pragma unroll
            for (int nt = 0; nt < 8; ++nt) {
                int n = wn + nt * 8 + grp;
                uint32_t b0 = Ws[n * XPITCH + kw + tig];
                uint32_t b1 = Ws[n * XPITCH + kw + tig + 4];
                mma_bf16(acc[0][nt], af[0][0], af[0][1], af[0][2], af[0][3], b0, b1);
                mma_bf16(acc[1][nt], af[1][0], af[1][1], af[1][2], af[1][3], b0, b1);
            }
        }
    }

    // epilogue: bias + ReLU; bf16 + fp8 shadow stores
#pragma unroll
    for (int mt = 0; mt < 2; ++mt) {
        int r0g = rowBase + wr + mt * 16 + grp;
        int r1g = r0g + 8;
#pragma unroll
        for (int nt = 0; nt < 8; ++nt) {
            int col = wn + nt * 8 + 2 * tig;
            float2 bv = *(const float2*)&bias[col];
            if (r0g < M) {
                float vx = fmaxf(acc[mt][nt][0] + bv.x, 0.0f);
                float vy = fmaxf(acc[mt][nt][1] + bv.y, 0.0f);
                __nv_bfloat162 hb = __floats2bfloat162_rn(vx, vy);
                *(__nv_bfloat162*)&Cb[(size_t)r0g * K_DIM + col] = hb;
                unsigned short p;
                asm("cvt.rn.satfinite.e4m3x2.f32 %0, %1, %2;" : "=h"(p) : "f"(vy), "f"(vx));
                *(unsigned short*)(C8 + (size_t)r0g * K_DIM + col) = p;
            }
            if (r1g < M) {
                float vx = fmaxf(acc[mt][nt][2] + bv.x, 0.0f);
                float vy = fmaxf(acc[mt][nt][3] + bv.y, 0.0f);
                __nv_bfloat162 hb = __floats2bfloat162_rn(vx, vy);
                *(__nv_bfloat162*)&Cb[(size_t)r1g * K_DIM + col] = hb;
                unsigned short p;
                asm("cvt.rn.satfinite.e4m3x2.f32 %0, %1, %2;" : "=h"(p) : "f"(vy), "f"(vx));
                *(unsigned short*)(C8 + (size_t)r1g * K_DIM + col) = p;
            }
        }
    }
}

// ---------------------------------------------------------------------------
// 5) fused SpMM2 + per-graph sums: block = 16 warps = 16 graph-sorted nodes.
__global__ __launch_bounds__(512)
void k_spmm_gs2(const uint8_t* __restrict__ X8,          // fp8 h1
                const __nv_bfloat16* __restrict__ H,      // bf16 h1
                const int* __restrict__ gid) {
    __shared__ float smean[16][K_DIM];
    __shared__ float sh1[16][K_DIM];
    __shared__ int sg[16];
    int wid = threadIdx.x >> 5, lane = threadIdx.x & 31;
    int node = blockIdx.x * 16 + wid;                     // 100000 = 6250*16
    int e0 = g_rowptr[node], e1 = g_rowptr[node + 1];
    int quarter = lane >> 3, sub8 = lane & 7;
    float4 a = gather_node4(X8, e0, e1, quarter, sub8);
    float inv = (e1 > e0) ? 1.0f / (float)(e1 - e0) : 0.0f;
    float4 mv;
    mv.x = a.x * inv; mv.y = a.y * inv; mv.z = a.z * inv; mv.w = a.w * inv;
    *(float4*)&smean[wid][sub8 * 16 + quarter * 4] = mv;
    uint2 u = *((const uint2*)(H + (size_t)node * K_DIM) + lane);
    float4 hv;
    hv.x = __uint_as_float(u.x << 16);
    hv.y = __uint_as_float(u.x & 0xFFFF0000u);
    hv.z = __uint_as_float(u.y << 16);
    hv.w = __uint_as_float(u.y & 0xFFFF0000u);
    *(float4*)&sh1[wid][lane * 4] = hv;
    if (lane == 0) sg[wid] = gid[node];
    __syncthreads();

    int t = threadIdx.x;
    if (t < 256) {
        int d = t & 127;
        float* dstArr = (t < 128) ? g_gs1 : g_gs2;
        int cur = sg[0];
        float acc = 0.0f;
#pragma unroll
        for (int w = 0; w < 16; ++w) {
            int g = sg[w];
            float v = (t < 128) ? sh1[w][d] : smean[w][d];
            if (g != cur) {
                atomicAdd(&dstArr[cur * K_DIM + d], acc);
                acc = 0.0f; cur = g;
            }
            acc += v;
        }
        atomicAdd(&dstArr[cur * K_DIM + d], acc);
    } else if (t == 256) {
        int cur = sg[0], c = 0;
#pragma unroll
        for (int w = 0; w < 16; ++w) {
            int g = sg[w];
            if (g != cur) { atomicAdd(&g_gcnt[cur], c); c = 0; cur = g; }
            ++c;
        }
        atomicAdd(&g_gcnt[cur], c);
    }
}

// ---------------------------------------------------------------------------
// 6) fused: hg = (gs1@W2s + gs2@W2n)/cnt + b2 ; out = [hg|perm]@Wc + bc
//    Re-zeroes gs1/gs2/gcnt for the next kernel_launch call.
__global__ void k_hgcls(const float* __restrict__ W2s, const float* __restrict__ W2n,
                        const float* __restrict__ b2,
                        const float* __restrict__ perm,
                        const float* __restrict__ Wc,
                        const float* __restrict__ bc,
                        float* __restrict__ out) {
    __shared__ float s1[K_DIM], s2[K_DIM], hgs[K_DIM];
    __shared__ float red[K_CLS];
    __shared__ int scnt;
    int g = blockIdx.x, d = threadIdx.x;
    s1[d] = g_gs1[g * K_DIM + d];
    s2[d] = g_gs2[g * K_DIM + d];
    if (d == 0) scnt = g_gcnt[g];
    if (d < K_CLS) red[d] = bc[d];
    __syncthreads();
    g_gs1[g * K_DIM + d] = 0.0f;       // zero-invariant for next call
    g_gs2[g * K_DIM + d] = 0.0f;
    if (d == 0) g_gcnt[g] = 0;
    float acc = 0.0f;
#pragma unroll 4
    for (int k = 0; k < K_DIM; ++k)
        acc += s1[k] * W2s[k * K_DIM + d] + s2[k] * W2n[k * K_DIM + d];
    int cnt = scnt;
    float inv = 1.0f / (float)(cnt > 1 ? cnt : 1);
    hgs[d] = acc * inv + b2[d];
    __syncthreads();
    if (d < 64) {
        int c = d & 7, seg = d >> 3;
        int k0 = seg * 32;
        float p = 0.0f;
#pragma unroll 4
        for (int k = k0; k < k0 + 32; ++k) {
            float val = (k < K_DIM) ? hgs[k] : perm[g * K_DIM + (k - K_DIM)];
            p += val * Wc[k * K_CLS + c];
        }
        atomicAdd(&red[c], p);
    }
    __syncthreads();
    if (d < K_CLS) out[g * K_CLS + d] = red[d];
}

// ---------------------------------------------------------------------------
extern "C" void kernel_launch(void* const* d_in, const int* in_sizes, int n_in,
                              void* d_out, int out_size) {
    const float* h    = (const float*)d_in[0];
    const float* perm = (const float*)d_in[1];
    const int*   src  = (const int*)  d_in[2];
    const int*   dst  = (const int*)  d_in[3];
    const int*   gid  = (const int*)  d_in[4];
    const float* W1s  = (const float*)d_in[5];
    const float* W1n  = (const float*)d_in[6];
    const float* b1   = (const float*)d_in[7];
    const float* W2s  = (const float*)d_in[8];
    const float* W2n  = (const float*)d_in[9];
    const float* b2   = (const float*)d_in[10];
    const float* Wc   = (const float*)d_in[11];
    const float* bc   = (const float*)d_in[12];
    float* out = (float*)d_out;
    (void)in_sizes; (void)n_in; (void)out_size;

    __nv_bfloat16* hbb;     cudaGetSymbolAddress((void**)&hbb,   g_hb);
    __nv_bfloat16* mbb;     cudaGetSymbolAddress((void**)&mbb,   g_mb);
    __nv_bfloat16* h1bb;    cudaGetSymbolAddress((void**)&h1bb,  g_h1b);
    uint8_t* h8;            cudaGetSymbolAddress((void**)&h8,    g_h8);
    uint8_t* h18;           cudaGetSymbolAddress((void**)&h18,   g_h18);
    __nv_bfloat16* wbb;     cudaGetSymbolAddress((void**)&wbb,   g_wb);

    // CSR build (3 launches)
    k_prep<<<(K_QUADS + 255) / 256, 256>>>(h, hbb, h8, dst, W1s, W1n);
    k_scan<<<K_NB, 256>>>();
    k_fill<<<(K_EDGES + 255) / 256, 256>>>(src, dst);

    int spmmBlocks = (K_NODES * 32 + 255) / 256;
    int gemmBlocks = (K_NODES + 127) / 128;

    // layer 1
    k_spmm1<<<spmmBlocks, 256>>>(h8, mbb);
    k_gemm_bf16<<<gemmBlocks, 256>>>(hbb, mbb, wbb, b1, h1bb, h18, K_NODES);

    // layer 2 on graph means: fused SpMM2 + per-graph sums, then readout
    k_spmm_gs2<<<K_NODES / 16, 512>>>(h18, h1bb, gid);
    k_hgcls<<<K_GRAPHS, K_DIM>>>(W2s, W2n, b2, perm, Wc, bc, out);
}